// round 7
// baseline (speedup 1.0000x reference)
#include <cuda_runtime.h>
#include <cuda_bf16.h>
#include <math.h>

// Problem constants
#define T_STEPS 128
#define BATCH   64
#define NTOKEN  10000
#define NB      6
#define BS      100
#define NHID    600          // NB*BS
#define NH_MHA  4
#define DK_MHA  16
#define EMHA    64           // NH_MHA*DK_MHA
#define DK_INP  128
#define DEC_ELEMS 81920000L  // T*B*NTOKEN
#define HX_ELEMS  38400      // B*NHID

// -------------------- device scratch (no allocations allowed) --------------------
__device__ float g_outputs[T_STEPS * BATCH * NHID];   // hx per step, row = t*64+b
__device__ float g_gruT_ih[NB * BS * 3 * BS];         // [k][d][g]  (6,100,300)
__device__ float g_gruT_hh[NB * BS * 3 * BS];
__device__ float g_mhafcT[EMHA * BS];                 // [e][i]  (64,100)
__device__ float g_gateT[EMHA * BS];

// -------------------- one-time weight transposes --------------------
__global__ void prep_kernel(const float* __restrict__ w_ih, const float* __restrict__ w_hh,
                            const float* __restrict__ mfc, const float* __restrict__ mgate) {
    int i = blockIdx.x * blockDim.x + threadIdx.x;
    if (i < NB * 3 * BS * BS) {               // 180000: (6,300,100) -> (6,100,300)
        int k = i / (3 * BS * BS);
        int r = i % (3 * BS * BS);
        int g = r / BS;
        int d = r % BS;
        int dst = k * (BS * 3 * BS) + d * (3 * BS) + g;
        g_gruT_ih[dst] = w_ih[i];
        g_gruT_hh[dst] = w_hh[i];
    }
    if (i < BS * EMHA) {                      // 6400: (100,64) -> (64,100)
        int r = i / EMHA;
        int e = i % EMHA;
        g_mhafcT[e * BS + r] = mfc[i];
        g_gateT[e * BS + r]  = mgate[i];
    }
}

// -------------------- recurrence: one CTA per batch element --------------------
__device__ __forceinline__ float sigmoidf_(float x) { return 1.f / (1.f + expf(-x)); }

__global__ __launch_bounds__(1024, 1)
void rnn_kernel(const int* __restrict__ input, const float* __restrict__ hidden,
                const float* __restrict__ enc,
                const float* __restrict__ wq,     // (6,100,128)
                const float* __restrict__ wk,     // (2,600,128) slab 0 used
                const float* __restrict__ wv,     // (2,600,128) slab 0 used
                const float* __restrict__ fc_w,   // (100,128)
                const float* __restrict__ fc_b,   // (100,)
                const float* __restrict__ mwq,    // (6,100,64)
                const float* __restrict__ mwk,
                const float* __restrict__ mwv,
                const float* __restrict__ mfc_b,  // (100,)
                const float* __restrict__ mg_b,   // (100,)
                const float* __restrict__ b_ih,   // (6,300)
                const float* __restrict__ b_hh)   // (6,300)
{
    const int b   = blockIdx.x;
    const int tid = threadIdx.x;

    __shared__ float s_hx[NHID];
    __shared__ float s_x[NHID];
    __shared__ float s_qp[768];        // 6 x 128
    __shared__ float s_k0[128];
    __shared__ float s_v0[128];
    __shared__ float s_part[1024];
    __shared__ float s_p[104];
    __shared__ float s_a0[8];
    __shared__ float s_mask[8];
    __shared__ float s_iu[NHID];
    __shared__ float s_gx[1800];
    __shared__ float s_gh[1800];
    __shared__ float s_hn[NHID];
    __shared__ float s_qkv[1152];      // q[0..384), k[384..768), v[768..1152)
    __shared__ float s_aw[144];        // (4 heads, 6q, 6k)
    __shared__ float s_ao[384];
    __shared__ int   s_tok;

    if (tid < NHID) s_hx[tid] = hidden[b * NHID + tid];
    __syncthreads();

    for (int t = 0; t < T_STEPS; t++) {
        // ---- P0: token + embedding ----
        if (tid == 0) s_tok = input[t * BATCH + b];
        __syncthreads();
        {
            int tok = s_tok;
            if (tid < NHID) s_x[tid] = enc[(long)tok * NHID + tid];
        }
        __syncthreads();

        // ---- P1b: k0/v0 partial dots (x @ Wk0 / x @ Wv0), split 4 ways over d ----
        {
            int kv   = tid >> 9;        // 0: k, 1: v
            int part = (tid >> 7) & 3;  // 0..3 (150 each)
            int e    = tid & 127;
            const float* W = kv ? wv : wk;   // slab 0
            float acc = 0.f;
            int d0 = part * 150;
            #pragma unroll 5
            for (int d = d0; d < d0 + 150; d++) acc += s_x[d] * W[d * 128 + e];
            s_part[tid] = acc;
        }
        __syncthreads();

        // ---- P1c: reduce k0/v0 (256 thr) ; q_proj (768 thr) ----
        if (tid < 256) {
            int kv = tid >> 7, e = tid & 127;
            int base = kv * 512 + e;
            float s = s_part[base] + s_part[base + 128] + s_part[base + 256] + s_part[base + 384];
            if (kv == 0) s_k0[e] = s; else s_v0[e] = s;
        } else {
            int u = tid - 256;           // 0..767
            int n = u >> 7, e = u & 127;
            const float* W = wq + n * (BS * DK_INP) + e;
            const float* h = s_hx + n * BS;
            float acc = 0.f;
            #pragma unroll 4
            for (int d = 0; d < BS; d++) acc += h[d] * W[d * 128];
            s_qp[u] = acc;
        }
        __syncthreads();

        // ---- P2: attention scores (warps 0..5) + p = v0 @ fc^T (800 thr) ----
        {
            int w = tid >> 5, l = tid & 31;
            if (w < 6) {
                float acc = s_qp[w * 128 + l]      * s_k0[l]
                          + s_qp[w * 128 + l + 32] * s_k0[l + 32]
                          + s_qp[w * 128 + l + 64] * s_k0[l + 64]
                          + s_qp[w * 128 + l + 96] * s_k0[l + 96];
                #pragma unroll
                for (int o = 16; o > 0; o >>= 1) acc += __shfl_xor_sync(0xffffffffu, acc, o);
                if (l == 0) s_a0[w] = sigmoidf_(acc * 0.08838834764831845f); // 1/sqrt(128)
            } else if (tid >= 224) {
                int u = tid - 224;           // 0..799
                int i = u >> 3, part = u & 7;
                const float* F  = fc_w + i * 128 + part * 16;
                const float* vv = s_v0 + part * 16;
                float acc = 0.f;
                #pragma unroll
                for (int j = 0; j < 16; j++) acc += vv[j] * F[j];
                acc += __shfl_xor_sync(0xffffffffu, acc, 1);
                acc += __shfl_xor_sync(0xffffffffu, acc, 2);
                acc += __shfl_xor_sync(0xffffffffu, acc, 4);
                if (part == 0) s_p[i] = acc;
            }
        }
        __syncthreads();

        // ---- P2b: top-k mask (thread 0) + inp_use (600 thr) ----
        if (tid == 0) {
            float v[6];
            #pragma unroll
            for (int n = 0; n < 6; n++) v[n] = s_a0[n];
            #pragma unroll
            for (int a = 0; a < 6; a++)
                #pragma unroll
                for (int c = a + 1; c < 6; c++)
                    if (v[c] > v[a]) { float tmp = v[a]; v[a] = v[c]; v[c] = tmp; }
            float thr = v[3] - 0.01f;   // 4th largest - 0.01
            #pragma unroll
            for (int n = 0; n < 6; n++) s_mask[n] = (s_a0[n] > thr) ? 1.f : 0.f;
        }
        if (tid >= 64 && tid < 64 + NHID) {
            int i = tid - 64;
            int n = i / BS, ii = i % BS;
            s_iu[i] = s_a0[n] * s_p[ii] + fc_b[ii];
        }
        __syncthreads();

        // ---- P4: GRU gate matvecs: gx = iu@W_ihT + b_ih ; gh = hx@W_hhT + b_hh ----
        for (int o = tid; o < 3600; o += 1024) {
            int half = (o >= 1800);
            int oo = half ? o - 1800 : o;
            int k = oo / 300, g = oo % 300;
            const float* WT  = (half ? g_gruT_hh : g_gruT_ih) + k * 30000 + g;
            const float* src = (half ? s_hx : s_iu) + k * BS;
            float acc = (half ? b_hh : b_ih)[oo];
            #pragma unroll 4
            for (int d = 0; d < BS; d++) acc += src[d] * WT[d * 300];
            if (half) s_gh[oo] = acc; else s_gx[oo] = acc;
        }
        __syncthreads();

        // ---- P5: GRU elementwise ----
        if (tid < NHID) {
            int k = tid / BS, j = tid % BS;
            int base = k * 300 + j;
            float r  = sigmoidf_(s_gx[base]       + s_gh[base]);
            float z  = sigmoidf_(s_gx[base + 100] + s_gh[base + 100]);
            float nn = tanhf(s_gx[base + 200] + r * s_gh[base + 200]);
            s_hn[tid] = (1.f - z) * nn + z * s_hx[tid];
        }
        __syncthreads();

        // ---- P6: MHA q/k/v projections (1152 dots of 100) ----
        for (int o = tid; o < 1152; o += 1024) {
            int which = o / 384, r2 = o % 384;
            int n = r2 >> 6, e = r2 & 63;
            const float* W = (which == 0 ? mwq : (which == 1 ? mwk : mwv)) + n * (BS * EMHA) + e;
            const float* h = s_hn + n * BS;
            float acc = 0.f;
            #pragma unroll 4
            for (int d = 0; d < BS; d++) acc += h[d] * W[d * 64];
            s_qkv[o] = acc;
        }
        __syncthreads();

        // ---- P7: attention scores + softmax ----
        if (tid < 144) {
            int h = tid / 36, r = tid % 36, i = r / 6, j = r % 6;
            const float* qv = s_qkv + i * 64 + h * 16;
            const float* kv = s_qkv + 384 + j * 64 + h * 16;
            float acc = 0.f;
            #pragma unroll
            for (int d = 0; d < 16; d++) acc += qv[d] * kv[d];
            s_aw[h * 36 + i * 6 + j] = acc * 0.25f;   // 1/sqrt(16)
        }
        __syncthreads();
        if (tid < 24) {
            int h = tid / 6, i = tid % 6;
            float* row = s_aw + h * 36 + i * 6;
            float m = row[0];
            #pragma unroll
            for (int j = 1; j < 6; j++) m = fmaxf(m, row[j]);
            float ex[6]; float ssum = 0.f;
            #pragma unroll
            for (int j = 0; j < 6; j++) { ex[j] = expf(row[j] - m); ssum += ex[j]; }
            float inv = 1.f / ssum;
            #pragma unroll
            for (int j = 0; j < 6; j++) row[j] = ex[j] * inv;
        }
        __syncthreads();

        // ---- P8: attn @ V ----
        if (tid < 384) {
            int n = tid >> 6, e = tid & 63, h = e >> 4;
            const float* aw = s_aw + h * 36 + n * 6;
            const float* vm = s_qkv + 768 + e;
            float acc = 0.f;
            #pragma unroll
            for (int j = 0; j < 6; j++) acc += aw[j] * vm[j * 64];
            s_ao[tid] = acc;
        }
        __syncthreads();

        // ---- P9: fc proj + gate + masked blend, write output ----
        if (tid < NHID) {
            int n = tid / BS, i = tid % BS;
            const float* ao = s_ao + n * 64;
            float pr = mfc_b[i], gt = mg_b[i];
            #pragma unroll 4
            for (int e = 0; e < 64; e++) {
                float a = ao[e];
                pr += a * g_mhafcT[e * BS + i];
                gt += a * g_gateT[e * BS + i];
            }
            float hatt = sigmoidf_(gt) * tanhf(pr);
            float m = s_mask[n];
            float nh = m * hatt + (1.f - m) * s_hx[tid];
            s_hx[tid] = nh;
            g_outputs[((long)t * BATCH + b) * NHID + tid] = nh;
        }
        __syncthreads();
    }
}

// -------------------- decoder GEMM: C[8192,10000] = outputs @ dec_w^T + dec_b --------------------
// 128x128 CTA tile, BK=8, 256 threads, 8x8 register tile, packed fma.rn.f32x2.
__global__ __launch_bounds__(256, 2)
void dec_kernel(const float* __restrict__ Bw, const float* __restrict__ bias,
                float* __restrict__ C)
{
    __shared__ __align__(16) float As[2][8][128];
    __shared__ __align__(16) float Bs[2][8][128];

    const int tid = threadIdx.x;
    const int bm = blockIdx.y * 128;
    const int bn = blockIdx.x * 128;

    const int lrow = tid >> 1;          // 0..127
    const int lk4  = (tid & 1) * 4;     // 0 or 4
    const float* Aptr = g_outputs + (long)(bm + lrow) * NHID + lk4;
    int brow = bn + lrow; if (brow > NTOKEN - 1) brow = NTOKEN - 1;
    const float* Bptr = Bw + (long)brow * NHID + lk4;

    const int tx = tid & 15, ty = tid >> 4;

    unsigned long long acc[8][4];
    #pragma unroll
    for (int i = 0; i < 8; i++)
        #pragma unroll
        for (int j = 0; j < 4; j++) acc[i][j] = 0ull;

    float4 ra = *(const float4*)Aptr;
    float4 rb = *(const float4*)Bptr;
    int buf = 0;
    As[0][lk4 + 0][lrow] = ra.x; As[0][lk4 + 1][lrow] = ra.y;
    As[0][lk4 + 2][lrow] = ra.z; As[0][lk4 + 3][lrow] = ra.w;
    Bs[0][lk4 + 0][lrow] = rb.x; Bs[0][lk4 + 1][lrow] = rb.y;
    Bs[0][lk4 + 2][lrow] = rb.z; Bs[0][lk4 + 3][lrow] = rb.w;
    __syncthreads();

    const int NKT = NHID / 8;   // 75
    for (int kt = 0; kt < NKT; kt++) {
        if (kt < NKT - 1) {
            ra = *(const float4*)(Aptr + (kt + 1) * 8);
            rb = *(const float4*)(Bptr + (kt + 1) * 8);
        }
        #pragma unroll
        for (int kk = 0; kk < 8; kk++) {
            float4 a0 = *(const float4*)(&As[buf][kk][ty * 8]);
            float4 a1 = *(const float4*)(&As[buf][kk][ty * 8 + 4]);
            ulonglong2 b0 = *(const ulonglong2*)(&Bs[buf][kk][tx * 8]);
            ulonglong2 b1 = *(const ulonglong2*)(&Bs[buf][kk][tx * 8 + 4]);
            float av[8] = {a0.x, a0.y, a0.z, a0.w, a1.x, a1.y, a1.z, a1.w};
            unsigned long long bb[4] = {b0.x, b0.y, b1.x, b1.y};
            #pragma unroll
            for (int i = 0; i < 8; i++) {
                unsigned long long aa;
                asm("mov.b64 %0, {%1, %1};" : "=l"(aa) : "r"(__float_as_uint(av[i])));
                #pragma unroll
                for (int j = 0; j < 4; j++)
                    asm("fma.rn.f32x2 %0, %1, %2, %0;" : "+l"(acc[i][j]) : "l"(aa), "l"(bb[j]));
            }
        }
        if (kt < NKT - 1) {
            int nb = buf ^ 1;
            As[nb][lk4 + 0][lrow] = ra.x; As[nb][lk4 + 1][lrow] = ra.y;
            As[nb][lk4 + 2][lrow] = ra.z; As[nb][lk4 + 3][lrow] = ra.w;
            Bs[nb][lk4 + 0][lrow] = rb.x; Bs[nb][lk4 + 1][lrow] = rb.y;
            Bs[nb][lk4 + 2][lrow] = rb.z; Bs[nb][lk4 + 3][lrow] = rb.w;
            __syncthreads();
            buf = nb;
        }
    }

    // epilogue
    const int n0 = bn + tx * 8;
    #pragma unroll
    for (int i = 0; i < 8; i++) {
        int m = bm + ty * 8 + i;
        float v[8];
        #pragma unroll
        for (int j = 0; j < 4; j++) {
            unsigned lo, hi;
            asm("mov.b64 {%0, %1}, %2;" : "=r"(lo), "=r"(hi) : "l"(acc[i][j]));
            v[2 * j]     = __uint_as_float(lo);
            v[2 * j + 1] = __uint_as_float(hi);
        }
        long base = (long)m * NTOKEN + n0;
        if (n0 + 8 <= NTOKEN) {
            #pragma unroll
            for (int j = 0; j < 8; j++) v[j] += bias[n0 + j];
            *(float4*)(C + base)     = make_float4(v[0], v[1], v[2], v[3]);
            *(float4*)(C + base + 4) = make_float4(v[4], v[5], v[6], v[7]);
        } else {
            for (int j = 0; j < 8; j++)
                if (n0 + j < NTOKEN) C[base + j] = v[j] + bias[n0 + j];
        }
    }
}

// -------------------- tail: hx_final + scalar loss, if d_out carries them --------------------
__global__ void tail_kernel(float* __restrict__ out, int out_size) {
    int i = blockIdx.x * blockDim.x + threadIdx.x;
    if (i < HX_ELEMS && (long)out_size >= DEC_ELEMS + HX_ELEMS)
        out[DEC_ELEMS + i] = g_outputs[(long)(T_STEPS - 1) * HX_ELEMS + i];
    if (i == 0 && (long)out_size >= DEC_ELEMS + HX_ELEMS + 1)
        out[DEC_ELEMS + HX_ELEMS] = 0.0f;
}

extern "C" void kernel_launch(void* const* d_in, const int* in_sizes, int n_in,
                              void* d_out, int out_size) {
    const int*   input      = (const int*)  d_in[0];
    const float* hidden     = (const float*)d_in[1];
    const float* encoder_w  = (const float*)d_in[2];
    const float* inp_wq     = (const float*)d_in[3];
    const float* inp_wk     = (const float*)d_in[4];
    const float* inp_wv     = (const float*)d_in[5];
    const float* inp_fc_w   = (const float*)d_in[6];
    const float* inp_fc_b   = (const float*)d_in[7];
    const float* mha_wq     = (const float*)d_in[8];
    const float* mha_wk     = (const float*)d_in[9];
    const float* mha_wv     = (const float*)d_in[10];
    const float* mha_fc_w   = (const float*)d_in[11];
    const float* mha_fc_b   = (const float*)d_in[12];
    const float* mha_gate_w = (const float*)d_in[13];
    const float* mha_gate_b = (const float*)d_in[14];
    const float* gru_w_ih   = (const float*)d_in[15];
    const float* gru_w_hh   = (const float*)d_in[16];
    const float* gru_b_ih   = (const float*)d_in[17];
    const float* gru_b_hh   = (const float*)d_in[18];
    const float* dec_w      = (const float*)d_in[19];
    const float* dec_b      = (const float*)d_in[20];
    float* out = (float*)d_out;

    prep_kernel<<<704, 256>>>(gru_w_ih, gru_w_hh, mha_fc_w, mha_gate_w);

    rnn_kernel<<<BATCH, 1024>>>(input, hidden, encoder_w,
                                inp_wq, inp_wk, inp_wv, inp_fc_w, inp_fc_b,
                                mha_wq, mha_wk, mha_wv, mha_fc_b, mha_gate_b,
                                gru_b_ih, gru_b_hh);

    dim3 dgrid((NTOKEN + 127) / 128, (T_STEPS * BATCH) / 128);
    dec_kernel<<<dgrid, 256>>>(dec_w, dec_b, out);

    tail_kernel<<<(HX_ELEMS + 255) / 256, 256>>>(out, out_size);
}

// round 9
// speedup vs baseline: 1.3006x; 1.3006x over previous
#include <cuda_runtime.h>
#include <cuda_bf16.h>
#include <math.h>

// Problem constants
#define T_STEPS 128
#define BATCH   64
#define NTOKEN  10000
#define NB      6
#define BS      100
#define NHID    600          // NB*BS
#define EMHA    64           // NH_MHA*DK_MHA
#define DEC_ELEMS 81920000L  // T*B*NTOKEN
#define HX_ELEMS  38400      // B*NHID

// -------------------- device scratch (no allocations allowed) --------------------
__device__ float g_outputs[T_STEPS * BATCH * NHID];   // hx per step, row = t*64+b
__device__ float g_gruT_ih[NB * BS * 3 * BS];         // [k][d][g]  (6,100,300)
__device__ float g_gruT_hh[NB * BS * 3 * BS];
__device__ float g_mhafcT[EMHA * BS];                 // [e][i]  (64,100)
__device__ float g_gateT[EMHA * BS];

// -------------------- one-time weight transposes --------------------
__global__ void prep_kernel(const float* __restrict__ w_ih, const float* __restrict__ w_hh,
                            const float* __restrict__ mfc, const float* __restrict__ mgate) {
    int i = blockIdx.x * blockDim.x + threadIdx.x;
    if (i < NB * 3 * BS * BS) {               // 180000: (6,300,100) -> (6,100,300)
        int k = i / (3 * BS * BS);
        int r = i % (3 * BS * BS);
        int g = r / BS;
        int d = r % BS;
        int dst = k * (BS * 3 * BS) + d * (3 * BS) + g;
        g_gruT_ih[dst] = w_ih[i];
        g_gruT_hh[dst] = w_hh[i];
    }
    if (i < BS * EMHA) {                      // 6400: (100,64) -> (64,100)
        int r = i / EMHA;
        int e = i % EMHA;
        g_mhafcT[e * BS + r] = mfc[i];
        g_gateT[e * BS + r]  = mgate[i];
    }
}

// -------------------- helpers --------------------
__device__ __forceinline__ float sigmoidf_(float x) { return 1.f / (1.f + expf(-x)); }
__device__ __forceinline__ void ffma2(unsigned long long& a, unsigned long long x, unsigned long long y) {
    asm("fma.rn.f32x2 %0, %1, %2, %0;" : "+l"(a) : "l"(x), "l"(y));
}
__device__ __forceinline__ unsigned long long bc2(float x) {
    unsigned long long r;
    asm("mov.b64 %0, {%1, %1};" : "=l"(r) : "r"(__float_as_uint(x)));
    return r;
}
__device__ __forceinline__ float2 up2(unsigned long long a) {
    unsigned lo, hi;
    asm("mov.b64 {%0, %1}, %2;" : "=r"(lo), "=r"(hi) : "l"(a));
    return make_float2(__uint_as_float(lo), __uint_as_float(hi));
}

// -------------------- smem layout (floats) --------------------
#define OFF_HX    0        // [2][600]
#define OFF_X     1200     // [2][600]
#define OFF_IU    2400     // [2][600]
#define OFF_HN    3600     // [2][600]
#define OFF_GX    4800     // [2][1800]
#define OFF_GH    8400     // [2][1800]
#define OFF_RED   12000    // 8192
#define OFF_QKVP  20192    // [2part][2b][1152]
#define OFF_QKV   24800    // [2][1152]
#define OFF_K0    27104    // [2][128]
#define OFF_V0    27360    // [2][128]
#define OFF_QP    27616    // [2][768]
#define OFF_P     29152    // [2][104]
#define OFF_A0    29360    // [2][8]
#define OFF_MASK  29376    // [2][8]
#define OFF_AW    29392    // [2][144]
#define OFF_AO    29680    // [2][384]
#define OFF_FCT   30448    // 6400
#define OFF_GT    36848    // 6400
#define OFF_TOK   43248    // 256 ints
#define SMEM_FLOATS 43504
#define SMEM_BYTES  (SMEM_FLOATS * 4)

// -------------------- recurrence: one CTA per 2 batch elements --------------------
__global__ __launch_bounds__(1024, 1)
void rnn_kernel(const int* __restrict__ input, const float* __restrict__ hidden,
                const float* __restrict__ enc,
                const float* __restrict__ wq,     // (6,100,128)
                const float* __restrict__ wk,     // (2,600,128) slab 0 used
                const float* __restrict__ wv,     // (2,600,128) slab 0 used
                const float* __restrict__ fc_w,   // (100,128)
                const float* __restrict__ fc_b,   // (100,)
                const float* __restrict__ mwq,    // (6,100,64)
                const float* __restrict__ mwk,
                const float* __restrict__ mwv,
                const float* __restrict__ mfc_b,  // (100,)
                const float* __restrict__ mg_b,   // (100,)
                const float* __restrict__ b_ih,   // (6,300)
                const float* __restrict__ b_hh)   // (6,300)
{
    const int b0  = blockIdx.x * 2;
    const int tid = threadIdx.x;

    extern __shared__ float smem[];
    float* s_hx   = smem + OFF_HX;
    float* s_x    = smem + OFF_X;
    float* s_iu   = smem + OFF_IU;
    float* s_hn   = smem + OFF_HN;
    float* s_gx   = smem + OFF_GX;
    float* s_gh   = smem + OFF_GH;
    float* s_red  = smem + OFF_RED;
    float* s_qkvp = smem + OFF_QKVP;
    float* s_qkv  = smem + OFF_QKV;
    float* s_k0   = smem + OFF_K0;
    float* s_v0   = smem + OFF_V0;
    float* s_qp   = smem + OFF_QP;
    float* s_p    = smem + OFF_P;
    float* s_a0   = smem + OFF_A0;
    float* s_mask = smem + OFF_MASK;
    float* s_aw   = smem + OFF_AW;
    float* s_ao   = smem + OFF_AO;
    float* s_fcT  = smem + OFF_FCT;
    float* s_gT   = smem + OFF_GT;
    int*   s_tok  = (int*)(smem + OFF_TOK);

    // preload: hx, cached fc/gate transposes, all tokens
    for (int j = tid; j < 1200; j += 1024)
        s_hx[j] = hidden[(long)(b0 + j / 600) * NHID + (j % 600)];
    for (int j = tid; j < 6400; j += 1024) {
        s_fcT[j] = g_mhafcT[j];
        s_gT[j]  = g_gateT[j];
    }
    if (tid < 256) {
        int t = tid >> 1, bb = tid & 1;
        s_tok[tid] = input[t * BATCH + b0 + bb];
    }
    __syncthreads();

    const int w    = tid >> 5;
    const int lane = tid & 31;
    const int l4   = lane * 4;

    for (int t = 0; t < T_STEPS; t++) {
        // ---- P0: embedding load (float4) ----
        if (tid < 300) {
            int bb = tid / 150, j = tid % 150;
            long tok = s_tok[t * 2 + bb];
            *(float4*)(s_x + bb * 600 + j * 4) = *(const float4*)(enc + tok * NHID + j * 4);
        }
        __syncthreads();

        // ---- Phase A: k0/v0 partials (warps 0-19) + q_proj partials (warps 20-31) ----
        if (w < 20) {
            int kv = w / 10, ws = w % 10;
            const float* W = kv ? wv : wk;   // slab 0
            unsigned long long a00 = 0, a01 = 0, a10 = 0, a11 = 0;
            for (int d = ws; d < 600; d += 10) {
                ulonglong2 wt = *(const ulonglong2*)(W + d * 128 + l4);
                unsigned long long x0 = bc2(s_x[d]);
                unsigned long long x1 = bc2(s_x[600 + d]);
                ffma2(a00, x0, wt.x); ffma2(a01, x0, wt.y);
                ffma2(a10, x1, wt.x); ffma2(a11, x1, wt.y);
            }
            float2 p0 = up2(a00), p1 = up2(a01);
            *(float4*)(s_red + ((kv * 10 + ws) * 2 + 0) * 128 + l4) = make_float4(p0.x, p0.y, p1.x, p1.y);
            p0 = up2(a10); p1 = up2(a11);
            *(float4*)(s_red + ((kv * 10 + ws) * 2 + 1) * 128 + l4) = make_float4(p0.x, p0.y, p1.x, p1.y);
        } else {
            int u = w - 20, n = u >> 1, dp = u & 1;
            const float* W  = wq + (n * 100 + dp * 50) * 128;
            const float* h0 = s_hx + n * 100 + dp * 50;
            unsigned long long a00 = 0, a01 = 0, a10 = 0, a11 = 0;
            #pragma unroll 2
            for (int d = 0; d < 50; d++) {
                ulonglong2 wt = *(const ulonglong2*)(W + d * 128 + l4);
                unsigned long long x0 = bc2(h0[d]);
                unsigned long long x1 = bc2(h0[600 + d]);
                ffma2(a00, x0, wt.x); ffma2(a01, x0, wt.y);
                ffma2(a10, x1, wt.x); ffma2(a11, x1, wt.y);
            }
            float2 p0 = up2(a00), p1 = up2(a01);
            *(float4*)(s_red + 5120 + ((n * 2 + dp) * 2 + 0) * 128 + l4) = make_float4(p0.x, p0.y, p1.x, p1.y);
            p0 = up2(a10); p1 = up2(a11);
            *(float4*)(s_red + 5120 + ((n * 2 + dp) * 2 + 1) * 128 + l4) = make_float4(p0.x, p0.y, p1.x, p1.y);
        }
        __syncthreads();

        // ---- Reduce: k0/v0 (sum 10) and qp (sum 2) ----
        for (int j = tid; j < 2048; j += 1024) {
            if (j < 512) {
                int kv = j >> 8, bb = (j >> 7) & 1, e = j & 127;
                float s = 0.f;
                #pragma unroll
                for (int ws = 0; ws < 10; ws++) s += s_red[((kv * 10 + ws) * 2 + bb) * 128 + e];
                (kv ? s_v0 : s_k0)[bb * 128 + e] = s;
            } else {
                int q = j - 512;
                int n = q >> 8, bb = (q >> 7) & 1, e = q & 127;
                s_qp[bb * 768 + n * 128 + e] =
                    s_red[5120 + ((n * 2 + 0) * 2 + bb) * 128 + e] +
                    s_red[5120 + ((n * 2 + 1) * 2 + bb) * 128 + e];
            }
        }
        __syncthreads();

        // ---- P2: scores (warps 0-11) + p = v0 @ fc^T (warps 12-31) ----
        if (w < 12) {
            int bb = w / 6, n = w % 6;
            const float* qv = s_qp + bb * 768 + n * 128;
            const float* k0 = s_k0 + bb * 128;
            float acc = qv[lane] * k0[lane] + qv[lane + 32] * k0[lane + 32]
                      + qv[lane + 64] * k0[lane + 64] + qv[lane + 96] * k0[lane + 96];
            #pragma unroll
            for (int o = 16; o > 0; o >>= 1) acc += __shfl_xor_sync(0xffffffffu, acc, o);
            if (lane == 0) s_a0[bb * 8 + n] = sigmoidf_(acc * 0.08838834764831845f);
        } else {
            int base = (w - 12) * 10;
            #pragma unroll 2
            for (int r = 0; r < 10; r++) {
                int pair = base + r;
                int bb = pair / 100, i = pair % 100;
                float4 f = *(const float4*)(fc_w + i * 128 + l4);
                const float* vv = s_v0 + bb * 128 + l4;
                float acc = f.x * vv[0] + f.y * vv[1] + f.z * vv[2] + f.w * vv[3];
                #pragma unroll
                for (int o = 16; o > 0; o >>= 1) acc += __shfl_xor_sync(0xffffffffu, acc, o);
                if (lane == 0) s_p[bb * 104 + i] = acc;
            }
        }
        __syncthreads();

        // ---- P2b: top-k mask + inp_use ----
        if (tid < 2) {
            int bb = tid;
            float v[6];
            #pragma unroll
            for (int n = 0; n < 6; n++) v[n] = s_a0[bb * 8 + n];
            #pragma unroll
            for (int a = 0; a < 6; a++)
                #pragma unroll
                for (int c = a + 1; c < 6; c++)
                    if (v[c] > v[a]) { float tmp = v[a]; v[a] = v[c]; v[c] = tmp; }
            float thr = v[3] - 0.01f;
            #pragma unroll
            for (int n = 0; n < 6; n++) s_mask[bb * 8 + n] = (s_a0[bb * 8 + n] > thr) ? 1.f : 0.f;
        }
        for (int j = tid; j < 1200; j += 1024) {
            int bb = j / 600, i = j % 600, n = i / 100, ii = i % 100;
            s_iu[bb * 600 + i] = s_a0[bb * 8 + n] * s_p[bb * 104 + ii] + fc_b[ii];
        }
        __syncthreads();

        // ---- P4: GRU gate matvecs (900 tasks, 4 outputs x 2 batches each) ----
        if (tid < 900) {
            int h = tid / 450, r = tid % 450, k = r / 75, g = (r % 75) * 4;
            const float* WT = (h ? g_gruT_hh : g_gruT_ih) + k * 30000 + g;
            const float* s0 = (h ? s_hx : s_iu) + k * 100;
            const float* bias = (h ? b_hh : b_ih) + k * 300 + g;
            unsigned long long a00 = 0, a01 = 0, a10 = 0, a11 = 0;
            #pragma unroll 4
            for (int d = 0; d < 100; d++) {
                ulonglong2 wt = *(const ulonglong2*)(WT + d * 300);
                unsigned long long x0 = bc2(s0[d]);
                unsigned long long x1 = bc2(s0[600 + d]);
                ffma2(a00, x0, wt.x); ffma2(a01, x0, wt.y);
                ffma2(a10, x1, wt.x); ffma2(a11, x1, wt.y);
            }
            float4 bi = *(const float4*)bias;
            float* dst = h ? s_gh : s_gx;
            float2 p0 = up2(a00), p1 = up2(a01);
            *(float4*)(dst + k * 300 + g) =
                make_float4(p0.x + bi.x, p0.y + bi.y, p1.x + bi.z, p1.y + bi.w);
            p0 = up2(a10); p1 = up2(a11);
            *(float4*)(dst + 1800 + k * 300 + g) =
                make_float4(p0.x + bi.x, p0.y + bi.y, p1.x + bi.z, p1.y + bi.w);
        }
        __syncthreads();

        // ---- P5: GRU elementwise ----
        for (int j = tid; j < 1200; j += 1024) {
            int bb = j / 600, i = j % 600, k = i / 100, jj = i % 100;
            int base = bb * 1800 + k * 300 + jj;
            float r  = sigmoidf_(s_gx[base]       + s_gh[base]);
            float z  = sigmoidf_(s_gx[base + 100] + s_gh[base + 100]);
            float nn = tanhf(s_gx[base + 200] + r * s_gh[base + 200]);
            s_hn[bb * 600 + i] = (1.f - z) * nn + z * s_hx[bb * 600 + i];
        }
        __syncthreads();

        // ---- P6: MHA q/k/v projections (576 tasks, d split 2) ----
        if (tid < 576) {
            int part = tid / 288, r = tid % 288;
            int which = r / 96, n = (r % 96) / 16, e4 = (r % 16) * 4;
            const float* W = (which == 0 ? mwq : (which == 1 ? mwk : mwv))
                             + (n * 100 + part * 50) * 64 + e4;
            const float* h0 = s_hn + n * 100 + part * 50;
            unsigned long long a00 = 0, a01 = 0, a10 = 0, a11 = 0;
            #pragma unroll 2
            for (int d = 0; d < 50; d++) {
                ulonglong2 wt = *(const ulonglong2*)(W + d * 64);
                unsigned long long x0 = bc2(h0[d]);
                unsigned long long x1 = bc2(h0[600 + d]);
                ffma2(a00, x0, wt.x); ffma2(a01, x0, wt.y);
                ffma2(a10, x1, wt.x); ffma2(a11, x1, wt.y);
            }
            int o = which * 384 + n * 64 + e4;
            float2 p0 = up2(a00), p1 = up2(a01);
            *(float4*)(s_qkvp + (part * 2 + 0) * 1152 + o) = make_float4(p0.x, p0.y, p1.x, p1.y);
            p0 = up2(a10); p1 = up2(a11);
            *(float4*)(s_qkvp + (part * 2 + 1) * 1152 + o) = make_float4(p0.x, p0.y, p1.x, p1.y);
        }
        __syncthreads();
        for (int j = tid; j < 2304; j += 1024) {
            int bb = j / 1152, o = j % 1152;
            s_qkv[bb * 1152 + o] = s_qkvp[(0 * 2 + bb) * 1152 + o] + s_qkvp[(1 * 2 + bb) * 1152 + o];
        }
        __syncthreads();

        // ---- P7: attention scores + softmax ----
        if (tid < 288) {
            int bb = tid / 144, r = tid % 144, h = r / 36, i = (r % 36) / 6, j = r % 6;
            const float* qv = s_qkv + bb * 1152 + i * 64 + h * 16;
            const float* kk = s_qkv + bb * 1152 + 384 + j * 64 + h * 16;
            float acc = 0.f;
            #pragma unroll
            for (int d = 0; d < 16; d++) acc += qv[d] * kk[d];
            s_aw[bb * 144 + h * 36 + i * 6 + j] = acc * 0.25f;
        }
        __syncthreads();
        if (tid < 48) {
            int bb = tid / 24, h = (tid % 24) / 6, i = tid % 6;
            float* row = s_aw + bb * 144 + h * 36 + i * 6;
            float m = row[0];
            #pragma unroll
            for (int j = 1; j < 6; j++) m = fmaxf(m, row[j]);
            float ex[6]; float ssum = 0.f;
            #pragma unroll
            for (int j = 0; j < 6; j++) { ex[j] = expf(row[j] - m); ssum += ex[j]; }
            float inv = 1.f / ssum;
            #pragma unroll
            for (int j = 0; j < 6; j++) row[j] = ex[j] * inv;
        }
        __syncthreads();

        // ---- P8: attn @ V ----
        if (tid < 768) {
            int bb = tid / 384, r = tid % 384, n = r / 64, e = r % 64, h = e / 16;
            const float* aw = s_aw + bb * 144 + h * 36 + n * 6;
            const float* vm = s_qkv + bb * 1152 + 768 + e;
            float acc = 0.f;
            #pragma unroll
            for (int j = 0; j < 6; j++) acc += aw[j] * vm[j * 64];
            s_ao[bb * 384 + r] = acc;
        }
        __syncthreads();

        // ---- P9: fc proj + gate + masked blend, write output ----
        if (tid < 300) {
            int bb = tid / 150, r = tid % 150, n = r / 25, i4 = (r % 25) * 4;
            const float* ao = s_ao + bb * 384 + n * 64;
            unsigned long long pr0 = 0, pr1 = 0, gt0 = 0, gt1 = 0;
            #pragma unroll 4
            for (int e = 0; e < 64; e++) {
                ulonglong2 f = *(const ulonglong2*)(s_fcT + e * 100 + i4);
                ulonglong2 g = *(const ulonglong2*)(s_gT + e * 100 + i4);
                unsigned long long a2 = bc2(ao[e]);
                ffma2(pr0, a2, f.x); ffma2(pr1, a2, f.y);
                ffma2(gt0, a2, g.x); ffma2(gt1, a2, g.y);
            }
            float2 pa = up2(pr0), pb = up2(pr1), ga = up2(gt0), gb = up2(gt1);
            float prv[4] = {pa.x, pa.y, pb.x, pb.y};
            float gtv[4] = {ga.x, ga.y, gb.x, gb.y};
            float m = s_mask[bb * 8 + n];
            float4 o4;
            float* ov = (float*)&o4;
            #pragma unroll
            for (int c = 0; c < 4; c++) {
                int i = i4 + c;
                float pr = prv[c] + mfc_b[i];
                float gt = gtv[c] + mg_b[i];
                float hatt = sigmoidf_(gt) * tanhf(pr);
                int hidx = bb * 600 + n * 100 + i;
                float nh = m * hatt + (1.f - m) * s_hx[hidx];
                s_hx[hidx] = nh;
                ov[c] = nh;
            }
            *(float4*)(g_outputs + ((long)t * BATCH + b0 + bb) * NHID + n * 100 + i4) = o4;
        }
        __syncthreads();
    }
}

// -------------------- decoder GEMM: C[8192,10000] = outputs @ dec_w^T + dec_b --------------------
__global__ __launch_bounds__(256, 2)
void dec_kernel(const float* __restrict__ Bw, const float* __restrict__ bias,
                float* __restrict__ C)
{
    __shared__ __align__(16) float As[2][8][128];
    __shared__ __align__(16) float Bs[2][8][128];

    const int tid = threadIdx.x;
    const int bm = blockIdx.y * 128;
    const int bn = blockIdx.x * 128;

    const int lrow = tid >> 1;
    const int lk4  = (tid & 1) * 4;
    const float* Aptr = g_outputs + (long)(bm + lrow) * NHID + lk4;
    int brow = bn + lrow; if (brow > NTOKEN - 1) brow = NTOKEN - 1;
    const float* Bptr = Bw + (long)brow * NHID + lk4;

    const int tx = tid & 15, ty = tid >> 4;

    unsigned long long acc[8][4];
    #pragma unroll
    for (int i = 0; i < 8; i++)
        #pragma unroll
        for (int j = 0; j < 4; j++) acc[i][j] = 0ull;

    float4 ra = *(const float4*)Aptr;
    float4 rb = *(const float4*)Bptr;
    int buf = 0;
    As[0][lk4 + 0][lrow] = ra.x; As[0][lk4 + 1][lrow] = ra.y;
    As[0][lk4 + 2][lrow] = ra.z; As[0][lk4 + 3][lrow] = ra.w;
    Bs[0][lk4 + 0][lrow] = rb.x; Bs[0][lk4 + 1][lrow] = rb.y;
    Bs[0][lk4 + 2][lrow] = rb.z; Bs[0][lk4 + 3][lrow] = rb.w;
    __syncthreads();

    const int NKT = NHID / 8;   // 75
    for (int kt = 0; kt < NKT; kt++) {
        if (kt < NKT - 1) {
            ra = *(const float4*)(Aptr + (kt + 1) * 8);
            rb = *(const float4*)(Bptr + (kt + 1) * 8);
        }
        #pragma unroll
        for (int kk = 0; kk < 8; kk++) {
            float4 a0 = *(const float4*)(&As[buf][kk][ty * 8]);
            float4 a1 = *(const float4*)(&As[buf][kk][ty * 8 + 4]);
            ulonglong2 b0 = *(const ulonglong2*)(&Bs[buf][kk][tx * 8]);
            ulonglong2 b1 = *(const ulonglong2*)(&Bs[buf][kk][tx * 8 + 4]);
            float av[8] = {a0.x, a0.y, a0.z, a0.w, a1.x, a1.y, a1.z, a1.w};
            unsigned long long bb[4] = {b0.x, b0.y, b1.x, b1.y};
            #pragma unroll
            for (int i = 0; i < 8; i++) {
                unsigned long long aa;
                asm("mov.b64 %0, {%1, %1};" : "=l"(aa) : "r"(__float_as_uint(av[i])));
                #pragma unroll
                for (int j = 0; j < 4; j++)
                    asm("fma.rn.f32x2 %0, %1, %2, %0;" : "+l"(acc[i][j]) : "l"(aa), "l"(bb[j]));
            }
        }
        if (kt < NKT - 1) {
            int nb = buf ^ 1;
            As[nb][lk4 + 0][lrow] = ra.x; As[nb][lk4 + 1][lrow] = ra.y;
            As[nb][lk4 + 2][lrow] = ra.z; As[nb][lk4 + 3][lrow] = ra.w;
            Bs[nb][lk4 + 0][lrow] = rb.x; Bs[nb][lk4 + 1][lrow] = rb.y;
            Bs[nb][lk4 + 2][lrow] = rb.z; Bs[nb][lk4 + 3][lrow] = rb.w;
            __syncthreads();
            buf = nb;
        }
    }

    const int n0 = bn + tx * 8;
    #pragma unroll
    for (int i = 0; i < 8; i++) {
        int m = bm + ty * 8 + i;
        float v[8];
        #pragma unroll
        for (int j = 0; j < 4; j++) {
            unsigned lo, hi;
            asm("mov.b64 {%0, %1}, %2;" : "=r"(lo), "=r"(hi) : "l"(acc[i][j]));
            v[2 * j]     = __uint_as_float(lo);
            v[2 * j + 1] = __uint_as_float(hi);
        }
        long base = (long)m * NTOKEN + n0;
        if (n0 + 8 <= NTOKEN) {
            #pragma unroll
            for (int j = 0; j < 8; j++) v[j] += bias[n0 + j];
            *(float4*)(C + base)     = make_float4(v[0], v[1], v[2], v[3]);
            *(float4*)(C + base + 4) = make_float4(v[4], v[5], v[6], v[7]);
        } else {
            for (int j = 0; j < 8; j++)
                if (n0 + j < NTOKEN) C[base + j] = v[j] + bias[n0 + j];
        }
    }
}

// -------------------- tail: hx_final + scalar loss, if d_out carries them --------------------
__global__ void tail_kernel(float* __restrict__ out, int out_size) {
    int i = blockIdx.x * blockDim.x + threadIdx.x;
    if (i < HX_ELEMS && (long)out_size >= DEC_ELEMS + HX_ELEMS)
        out[DEC_ELEMS + i] = g_outputs[(long)(T_STEPS - 1) * HX_ELEMS + i];
    if (i == 0 && (long)out_size >= DEC_ELEMS + HX_ELEMS + 1)
        out[DEC_ELEMS + HX_ELEMS] = 0.0f;
}

extern "C" void kernel_launch(void* const* d_in, const int* in_sizes, int n_in,
                              void* d_out, int out_size) {
    const int*   input      = (const int*)  d_in[0];
    const float* hidden     = (const float*)d_in[1];
    const float* encoder_w  = (const float*)d_in[2];
    const float* inp_wq     = (const float*)d_in[3];
    const float* inp_wk     = (const float*)d_in[4];
    const float* inp_wv     = (const float*)d_in[5];
    const float* inp_fc_w   = (const float*)d_in[6];
    const float* inp_fc_b   = (const float*)d_in[7];
    const float* mha_wq     = (const float*)d_in[8];
    const float* mha_wk     = (const float*)d_in[9];
    const float* mha_wv     = (const float*)d_in[10];
    const float* mha_fc_w   = (const float*)d_in[11];
    const float* mha_fc_b   = (const float*)d_in[12];
    const float* mha_gate_w = (const float*)d_in[13];
    const float* mha_gate_b = (const float*)d_in[14];
    const float* gru_w_ih   = (const float*)d_in[15];
    const float* gru_w_hh   = (const float*)d_in[16];
    const float* gru_b_ih   = (const float*)d_in[17];
    const float* gru_b_hh   = (const float*)d_in[18];
    const float* dec_w      = (const float*)d_in[19];
    const float* dec_b      = (const float*)d_in[20];
    float* out = (float*)d_out;

    cudaFuncSetAttribute(rnn_kernel, cudaFuncAttributeMaxDynamicSharedMemorySize, SMEM_BYTES);

    prep_kernel<<<704, 256>>>(gru_w_ih, gru_w_hh, mha_fc_w, mha_gate_w);

    rnn_kernel<<<BATCH / 2, 1024, SMEM_BYTES>>>(input, hidden, encoder_w,
                                inp_wq, inp_wk, inp_wv, inp_fc_w, inp_fc_b,
                                mha_wq, mha_wk, mha_wv, mha_fc_b, mha_gate_b,
                                gru_b_ih, gru_b_hh);

    dim3 dgrid((NTOKEN + 127) / 128, (T_STEPS * BATCH) / 128);
    dec_kernel<<<dgrid, 256>>>(dec_w, dec_b, out);

    tail_kernel<<<(HX_ELEMS + 255) / 256, 256>>>(out, out_size);
}

// round 10
// speedup vs baseline: 1.3146x; 1.0107x over previous
#include <cuda_runtime.h>
#include <cuda_bf16.h>
#include <math.h>

// Problem constants
#define T_STEPS 128
#define BATCH   64
#define NTOKEN  10000
#define NB      6
#define BS      100
#define NHID    600          // NB*BS
#define EMHA    64           // NH_MHA*DK_MHA
#define DEC_ELEMS 81920000L  // T*B*NTOKEN
#define HX_ELEMS  38400      // B*NHID

// -------------------- device scratch (no allocations allowed) --------------------
__device__ float g_outputs[T_STEPS * BATCH * NHID];   // hx per step, row = t*64+b
__device__ float g_gruT_ih[NB * BS * 3 * BS];         // [k][d][g]  (6,100,300)
__device__ float g_gruT_hh[NB * BS * 3 * BS];
__device__ float g_mhafcT[EMHA * BS];                 // [e][i]  (64,100)
__device__ float g_gateT[EMHA * BS];

// -------------------- one-time weight transposes --------------------
__global__ void prep_kernel(const float* __restrict__ w_ih, const float* __restrict__ w_hh,
                            const float* __restrict__ mfc, const float* __restrict__ mgate) {
    int i = blockIdx.x * blockDim.x + threadIdx.x;
    if (i < NB * 3 * BS * BS) {               // 180000: (6,300,100) -> (6,100,300)
        int k = i / (3 * BS * BS);
        int r = i % (3 * BS * BS);
        int g = r / BS;
        int d = r % BS;
        int dst = k * (BS * 3 * BS) + d * (3 * BS) + g;
        g_gruT_ih[dst] = w_ih[i];
        g_gruT_hh[dst] = w_hh[i];
    }
    if (i < BS * EMHA) {                      // 6400: (100,64) -> (64,100)
        int r = i / EMHA;
        int e = i % EMHA;
        g_mhafcT[e * BS + r] = mfc[i];
        g_gateT[e * BS + r]  = mgate[i];
    }
}

// -------------------- helpers --------------------
__device__ __forceinline__ float sigmoidf_(float x) { return 1.f / (1.f + expf(-x)); }
__device__ __forceinline__ void ffma2(unsigned long long& a, unsigned long long x, unsigned long long y) {
    asm("fma.rn.f32x2 %0, %1, %2, %0;" : "+l"(a) : "l"(x), "l"(y));
}
__device__ __forceinline__ unsigned long long bc2(float x) {
    unsigned long long r;
    asm("mov.b64 %0, {%1, %1};" : "=l"(r) : "r"(__float_as_uint(x)));
    return r;
}
__device__ __forceinline__ float2 up2(unsigned long long a) {
    unsigned lo, hi;
    asm("mov.b64 {%0, %1}, %2;" : "=r"(lo), "=r"(hi) : "l"(a));
    return make_float2(__uint_as_float(lo), __uint_as_float(hi));
}

// -------------------- smem layout (floats) --------------------
#define OFF_HX    0        // [2][600]
#define OFF_X     1200     // [2][600]
#define OFF_IU    2400     // [2][600]
#define OFF_HN    3600     // [2][600]
#define OFF_GX    4800     // [2][1800]
#define OFF_GH    8400     // [2][1800]
#define OFF_RED   12000    // 8192
#define OFF_QKVP  20192    // [2part][2b][1152]
#define OFF_QKV   24800    // [2][1152]
#define OFF_K0    27104    // [2][128]
#define OFF_V0    27360    // [2][128]
#define OFF_QP    27616    // [2][768]
#define OFF_P     29152    // [2][104]
#define OFF_A0    29360    // [2][8]
#define OFF_MASK  29376    // [2][8]
#define OFF_AW    29392    // [2][144]
#define OFF_AO    29680    // [2][384]
#define OFF_FCT   30448    // 6400
#define OFF_GT    36848    // 6400
#define OFF_TOK   43248    // 256 ints
#define SMEM_FLOATS 43504
#define SMEM_BYTES  (SMEM_FLOATS * 4)

// -------------------- recurrence: one CTA per 2 batch elements --------------------
__global__ __launch_bounds__(1024, 1)
void rnn_kernel(const int* __restrict__ input, const float* __restrict__ hidden,
                const float* __restrict__ enc,
                const float* __restrict__ wq,     // (6,100,128)
                const float* __restrict__ wk,     // (2,600,128) slab 0 used
                const float* __restrict__ wv,     // (2,600,128) slab 0 used
                const float* __restrict__ fc_w,   // (100,128)
                const float* __restrict__ fc_b,   // (100,)
                const float* __restrict__ mwq,    // (6,100,64)
                const float* __restrict__ mwk,
                const float* __restrict__ mwv,
                const float* __restrict__ mfc_b,  // (100,)
                const float* __restrict__ mg_b,   // (100,)
                const float* __restrict__ b_ih,   // (6,300)
                const float* __restrict__ b_hh)   // (6,300)
{
    const int b0  = blockIdx.x * 2;
    const int tid = threadIdx.x;

    extern __shared__ float smem[];
    float* s_hx   = smem + OFF_HX;
    float* s_x    = smem + OFF_X;
    float* s_iu   = smem + OFF_IU;
    float* s_hn   = smem + OFF_HN;
    float* s_gx   = smem + OFF_GX;
    float* s_gh   = smem + OFF_GH;
    float* s_red  = smem + OFF_RED;
    float* s_qkvp = smem + OFF_QKVP;
    float* s_qkv  = smem + OFF_QKV;
    float* s_k0   = smem + OFF_K0;
    float* s_v0   = smem + OFF_V0;
    float* s_qp   = smem + OFF_QP;
    float* s_p    = smem + OFF_P;
    float* s_a0   = smem + OFF_A0;
    float* s_mask = smem + OFF_MASK;
    float* s_aw   = smem + OFF_AW;
    float* s_ao   = smem + OFF_AO;
    float* s_fcT  = smem + OFF_FCT;
    float* s_gT   = smem + OFF_GT;
    int*   s_tok  = (int*)(smem + OFF_TOK);

    // preload: hx, cached fc/gate transposes, all tokens
    for (int j = tid; j < 1200; j += 1024)
        s_hx[j] = hidden[(long)(b0 + j / 600) * NHID + (j % 600)];
    for (int j = tid; j < 6400; j += 1024) {
        s_fcT[j] = g_mhafcT[j];
        s_gT[j]  = g_gateT[j];
    }
    if (tid < 256) {
        int t = tid >> 1, bb = tid & 1;
        s_tok[tid] = input[t * BATCH + b0 + bb];
    }
    __syncthreads();

    const int w    = tid >> 5;
    const int lane = tid & 31;
    const int l4   = lane * 4;

    for (int t = 0; t < T_STEPS; t++) {
        // ---- P0: embedding load (float4) ----
        if (tid < 300) {
            int bb = tid / 150, j = tid % 150;
            long tok = s_tok[t * 2 + bb];
            *(float4*)(s_x + bb * 600 + j * 4) = *(const float4*)(enc + tok * NHID + j * 4);
        }
        __syncthreads();

        // ---- Phase A: k0/v0 partials (warps 0-19) + q_proj partials (warps 20-31) ----
        if (w < 20) {
            int kv = w / 10, ws = w % 10;
            const float* W = kv ? wv : wk;   // slab 0
            unsigned long long a00 = 0, a01 = 0, a10 = 0, a11 = 0;
            for (int d = ws; d < 600; d += 10) {
                ulonglong2 wt = *(const ulonglong2*)(W + d * 128 + l4);
                unsigned long long x0 = bc2(s_x[d]);
                unsigned long long x1 = bc2(s_x[600 + d]);
                ffma2(a00, x0, wt.x); ffma2(a01, x0, wt.y);
                ffma2(a10, x1, wt.x); ffma2(a11, x1, wt.y);
            }
            float2 p0 = up2(a00), p1 = up2(a01);
            *(float4*)(s_red + ((kv * 10 + ws) * 2 + 0) * 128 + l4) = make_float4(p0.x, p0.y, p1.x, p1.y);
            p0 = up2(a10); p1 = up2(a11);
            *(float4*)(s_red + ((kv * 10 + ws) * 2 + 1) * 128 + l4) = make_float4(p0.x, p0.y, p1.x, p1.y);
        } else {
            int u = w - 20, n = u >> 1, dp = u & 1;
            const float* W  = wq + (n * 100 + dp * 50) * 128;
            const float* h0 = s_hx + n * 100 + dp * 50;
            unsigned long long a00 = 0, a01 = 0, a10 = 0, a11 = 0;
            #pragma unroll 2
            for (int d = 0; d < 50; d++) {
                ulonglong2 wt = *(const ulonglong2*)(W + d * 128 + l4);
                unsigned long long x0 = bc2(h0[d]);
                unsigned long long x1 = bc2(h0[600 + d]);
                ffma2(a00, x0, wt.x); ffma2(a01, x0, wt.y);
                ffma2(a10, x1, wt.x); ffma2(a11, x1, wt.y);
            }
            float2 p0 = up2(a00), p1 = up2(a01);
            *(float4*)(s_red + 5120 + ((n * 2 + dp) * 2 + 0) * 128 + l4) = make_float4(p0.x, p0.y, p1.x, p1.y);
            p0 = up2(a10); p1 = up2(a11);
            *(float4*)(s_red + 5120 + ((n * 2 + dp) * 2 + 1) * 128 + l4) = make_float4(p0.x, p0.y, p1.x, p1.y);
        }
        __syncthreads();

        // ---- Reduce: k0/v0 (sum 10) and qp (sum 2) ----
        for (int j = tid; j < 2048; j += 1024) {
            if (j < 512) {
                int kv = j >> 8, bb = (j >> 7) & 1, e = j & 127;
                float s = 0.f;
                #pragma unroll
                for (int ws = 0; ws < 10; ws++) s += s_red[((kv * 10 + ws) * 2 + bb) * 128 + e];
                (kv ? s_v0 : s_k0)[bb * 128 + e] = s;
            } else {
                int q = j - 512;
                int n = q >> 8, bb = (q >> 7) & 1, e = q & 127;
                s_qp[bb * 768 + n * 128 + e] =
                    s_red[5120 + ((n * 2 + 0) * 2 + bb) * 128 + e] +
                    s_red[5120 + ((n * 2 + 1) * 2 + bb) * 128 + e];
            }
        }
        __syncthreads();

        // ---- P2: scores (warps 0-11) + p = v0 @ fc^T (warps 12-31) ----
        if (w < 12) {
            int bb = w / 6, n = w % 6;
            const float* qv = s_qp + bb * 768 + n * 128;
            const float* k0 = s_k0 + bb * 128;
            float acc = qv[lane] * k0[lane] + qv[lane + 32] * k0[lane + 32]
                      + qv[lane + 64] * k0[lane + 64] + qv[lane + 96] * k0[lane + 96];
            #pragma unroll
            for (int o = 16; o > 0; o >>= 1) acc += __shfl_xor_sync(0xffffffffu, acc, o);
            if (lane == 0) s_a0[bb * 8 + n] = sigmoidf_(acc * 0.08838834764831845f);
        } else {
            int base = (w - 12) * 10;
            #pragma unroll 2
            for (int r = 0; r < 10; r++) {
                int pair = base + r;
                int bb = pair / 100, i = pair % 100;
                float4 f = *(const float4*)(fc_w + i * 128 + l4);
                const float* vv = s_v0 + bb * 128 + l4;
                float acc = f.x * vv[0] + f.y * vv[1] + f.z * vv[2] + f.w * vv[3];
                #pragma unroll
                for (int o = 16; o > 0; o >>= 1) acc += __shfl_xor_sync(0xffffffffu, acc, o);
                if (lane == 0) s_p[bb * 104 + i] = acc;
            }
        }
        __syncthreads();

        // ---- P2b: top-k mask + inp_use ----
        if (tid < 2) {
            int bb = tid;
            float v[6];
            #pragma unroll
            for (int n = 0; n < 6; n++) v[n] = s_a0[bb * 8 + n];
            #pragma unroll
            for (int a = 0; a < 6; a++)
                #pragma unroll
                for (int c = a + 1; c < 6; c++)
                    if (v[c] > v[a]) { float tmp = v[a]; v[a] = v[c]; v[c] = tmp; }
            float thr = v[3] - 0.01f;
            #pragma unroll
            for (int n = 0; n < 6; n++) s_mask[bb * 8 + n] = (s_a0[bb * 8 + n] > thr) ? 1.f : 0.f;
        }
        for (int j = tid; j < 1200; j += 1024) {
            int bb = j / 600, i = j % 600, n = i / 100, ii = i % 100;
            s_iu[bb * 600 + i] = s_a0[bb * 8 + n] * s_p[bb * 104 + ii] + fc_b[ii];
        }
        __syncthreads();

        // ---- P4: GRU gate matvecs (900 tasks, 4 outputs x 2 batches each) ----
        if (tid < 900) {
            int h = tid / 450, r = tid % 450, k = r / 75, g = (r % 75) * 4;
            const float* WT = (h ? g_gruT_hh : g_gruT_ih) + k * 30000 + g;
            const float* s0 = (h ? s_hx : s_iu) + k * 100;
            const float* bias = (h ? b_hh : b_ih) + k * 300 + g;
            unsigned long long a00 = 0, a01 = 0, a10 = 0, a11 = 0;
            #pragma unroll 4
            for (int d = 0; d < 100; d++) {
                ulonglong2 wt = *(const ulonglong2*)(WT + d * 300);
                unsigned long long x0 = bc2(s0[d]);
                unsigned long long x1 = bc2(s0[600 + d]);
                ffma2(a00, x0, wt.x); ffma2(a01, x0, wt.y);
                ffma2(a10, x1, wt.x); ffma2(a11, x1, wt.y);
            }
            float4 bi = *(const float4*)bias;
            float* dst = h ? s_gh : s_gx;
            float2 p0 = up2(a00), p1 = up2(a01);
            *(float4*)(dst + k * 300 + g) =
                make_float4(p0.x + bi.x, p0.y + bi.y, p1.x + bi.z, p1.y + bi.w);
            p0 = up2(a10); p1 = up2(a11);
            *(float4*)(dst + 1800 + k * 300 + g) =
                make_float4(p0.x + bi.x, p0.y + bi.y, p1.x + bi.z, p1.y + bi.w);
        }
        __syncthreads();

        // ---- P5: GRU elementwise ----
        for (int j = tid; j < 1200; j += 1024) {
            int bb = j / 600, i = j % 600, k = i / 100, jj = i % 100;
            int base = bb * 1800 + k * 300 + jj;
            float r  = sigmoidf_(s_gx[base]       + s_gh[base]);
            float z  = sigmoidf_(s_gx[base + 100] + s_gh[base + 100]);
            float nn = tanhf(s_gx[base + 200] + r * s_gh[base + 200]);
            s_hn[bb * 600 + i] = (1.f - z) * nn + z * s_hx[bb * 600 + i];
        }
        __syncthreads();

        // ---- P6: MHA q/k/v projections (576 tasks, d split 2) ----
        if (tid < 576) {
            int part = tid / 288, r = tid % 288;
            int which = r / 96, n = (r % 96) / 16, e4 = (r % 16) * 4;
            const float* W = (which == 0 ? mwq : (which == 1 ? mwk : mwv))
                             + (n * 100 + part * 50) * 64 + e4;
            const float* h0 = s_hn + n * 100 + part * 50;
            unsigned long long a00 = 0, a01 = 0, a10 = 0, a11 = 0;
            #pragma unroll 2
            for (int d = 0; d < 50; d++) {
                ulonglong2 wt = *(const ulonglong2*)(W + d * 64);
                unsigned long long x0 = bc2(h0[d]);
                unsigned long long x1 = bc2(h0[600 + d]);
                ffma2(a00, x0, wt.x); ffma2(a01, x0, wt.y);
                ffma2(a10, x1, wt.x); ffma2(a11, x1, wt.y);
            }
            int o = which * 384 + n * 64 + e4;
            float2 p0 = up2(a00), p1 = up2(a01);
            *(float4*)(s_qkvp + (part * 2 + 0) * 1152 + o) = make_float4(p0.x, p0.y, p1.x, p1.y);
            p0 = up2(a10); p1 = up2(a11);
            *(float4*)(s_qkvp + (part * 2 + 1) * 1152 + o) = make_float4(p0.x, p0.y, p1.x, p1.y);
        }
        __syncthreads();
        for (int j = tid; j < 2304; j += 1024) {
            int bb = j / 1152, o = j % 1152;
            s_qkv[bb * 1152 + o] = s_qkvp[(0 * 2 + bb) * 1152 + o] + s_qkvp[(1 * 2 + bb) * 1152 + o];
        }
        __syncthreads();

        // ---- P7: attention scores + softmax ----
        if (tid < 288) {
            int bb = tid / 144, r = tid % 144, h = r / 36, i = (r % 36) / 6, j = r % 6;
            const float* qv = s_qkv + bb * 1152 + i * 64 + h * 16;
            const float* kk = s_qkv + bb * 1152 + 384 + j * 64 + h * 16;
            float acc = 0.f;
            #pragma unroll
            for (int d = 0; d < 16; d++) acc += qv[d] * kk[d];
            s_aw[bb * 144 + h * 36 + i * 6 + j] = acc * 0.25f;
        }
        __syncthreads();
        if (tid < 48) {
            int bb = tid / 24, h = (tid % 24) / 6, i = tid % 6;
            float* row = s_aw + bb * 144 + h * 36 + i * 6;
            float m = row[0];
            #pragma unroll
            for (int j = 1; j < 6; j++) m = fmaxf(m, row[j]);
            float ex[6]; float ssum = 0.f;
            #pragma unroll
            for (int j = 0; j < 6; j++) { ex[j] = expf(row[j] - m); ssum += ex[j]; }
            float inv = 1.f / ssum;
            #pragma unroll
            for (int j = 0; j < 6; j++) row[j] = ex[j] * inv;
        }
        __syncthreads();

        // ---- P8: attn @ V ----
        if (tid < 768) {
            int bb = tid / 384, r = tid % 384, n = r / 64, e = r % 64, h = e / 16;
            const float* aw = s_aw + bb * 144 + h * 36 + n * 6;
            const float* vm = s_qkv + bb * 1152 + 768 + e;
            float acc = 0.f;
            #pragma unroll
            for (int j = 0; j < 6; j++) acc += aw[j] * vm[j * 64];
            s_ao[bb * 384 + r] = acc;
        }
        __syncthreads();

        // ---- P9: fc proj + gate + masked blend, write output ----
        if (tid < 300) {
            int bb = tid / 150, r = tid % 150, n = r / 25, i4 = (r % 25) * 4;
            const float* ao = s_ao + bb * 384 + n * 64;
            unsigned long long pr0 = 0, pr1 = 0, gt0 = 0, gt1 = 0;
            #pragma unroll 4
            for (int e = 0; e < 64; e++) {
                ulonglong2 f = *(const ulonglong2*)(s_fcT + e * 100 + i4);
                ulonglong2 g = *(const ulonglong2*)(s_gT + e * 100 + i4);
                unsigned long long a2 = bc2(ao[e]);
                ffma2(pr0, a2, f.x); ffma2(pr1, a2, f.y);
                ffma2(gt0, a2, g.x); ffma2(gt1, a2, g.y);
            }
            float2 pa = up2(pr0), pb = up2(pr1), ga = up2(gt0), gb = up2(gt1);
            float prv[4] = {pa.x, pa.y, pb.x, pb.y};
            float gtv[4] = {ga.x, ga.y, gb.x, gb.y};
            float m = s_mask[bb * 8 + n];
            float4 o4;
            float* ov = (float*)&o4;
            #pragma unroll
            for (int c = 0; c < 4; c++) {
                int i = i4 + c;
                float pr = prv[c] + mfc_b[i];
                float gt = gtv[c] + mg_b[i];
                float hatt = sigmoidf_(gt) * tanhf(pr);
                int hidx = bb * 600 + n * 100 + i;
                float nh = m * hatt + (1.f - m) * s_hx[hidx];
                s_hx[hidx] = nh;
                ov[c] = nh;
            }
            *(float4*)(g_outputs + ((long)t * BATCH + b0 + bb) * NHID + n * 100 + i4) = o4;
        }
        __syncthreads();
    }
}

// -------------------- decoder GEMM: C[8192,10000] = outputs @ dec_w^T + dec_b --------------------
__global__ __launch_bounds__(256, 2)
void dec_kernel(const float* __restrict__ Bw, const float* __restrict__ bias,
                float* __restrict__ C)
{
    __shared__ __align__(16) float As[2][8][128];
    __shared__ __align__(16) float Bs[2][8][128];

    const int tid = threadIdx.x;
    const int bm = blockIdx.y * 128;
    const int bn = blockIdx.x * 128;

    const int lrow = tid >> 1;
    const int lk4  = (tid & 1) * 4;
    const float* Aptr = g_outputs + (long)(bm + lrow) * NHID + lk4;
    int brow = bn + lrow; if (brow > NTOKEN - 1) brow = NTOKEN - 1;
    const float* Bptr = Bw + (long)brow * NHID + lk4;

    const int tx = tid & 15, ty = tid >> 4;

    unsigned long long acc[8][4];
    #pragma unroll
    for (int i = 0; i < 8; i++)
        #pragma unroll
        for (int j = 0; j < 4; j++) acc[i][j] = 0ull;

    float4 ra = *(const float4*)Aptr;
    float4 rb = *(const float4*)Bptr;
    int buf = 0;
    As[0][lk4 + 0][lrow] = ra.x; As[0][lk4 + 1][lrow] = ra.y;
    As[0][lk4 + 2][lrow] = ra.z; As[0][lk4 + 3][lrow] = ra.w;
    Bs[0][lk4 + 0][lrow] = rb.x; Bs[0][lk4 + 1][lrow] = rb.y;
    Bs[0][lk4 + 2][lrow] = rb.z; Bs[0][lk4 + 3][lrow] = rb.w;
    __syncthreads();

    const int NKT = NHID / 8;   // 75
    for (int kt = 0; kt < NKT; kt++) {
        if (kt < NKT - 1) {
            ra = *(const float4*)(Aptr + (kt + 1) * 8);
            rb = *(const float4*)(Bptr + (kt + 1) * 8);
        }
        #pragma unroll
        for (int kk = 0; kk < 8; kk++) {
            float4 a0 = *(const float4*)(&As[buf][kk][ty * 8]);
            float4 a1 = *(const float4*)(&As[buf][kk][ty * 8 + 4]);
            ulonglong2 b0 = *(const ulonglong2*)(&Bs[buf][kk][tx * 8]);
            ulonglong2 b1 = *(const ulonglong2*)(&Bs[buf][kk][tx * 8 + 4]);
            float av[8] = {a0.x, a0.y, a0.z, a0.w, a1.x, a1.y, a1.z, a1.w};
            unsigned long long bb[4] = {b0.x, b0.y, b1.x, b1.y};
            #pragma unroll
            for (int i = 0; i < 8; i++) {
                unsigned long long aa;
                asm("mov.b64 %0, {%1, %1};" : "=l"(aa) : "r"(__float_as_uint(av[i])));
                #pragma unroll
                for (int j = 0; j < 4; j++)
                    asm("fma.rn.f32x2 %0, %1, %2, %0;" : "+l"(acc[i][j]) : "l"(aa), "l"(bb[j]));
            }
        }
        if (kt < NKT - 1) {
            int nb = buf ^ 1;
            As[nb][lk4 + 0][lrow] = ra.x; As[nb][lk4 + 1][lrow] = ra.y;
            As[nb][lk4 + 2][lrow] = ra.z; As[nb][lk4 + 3][lrow] = ra.w;
            Bs[nb][lk4 + 0][lrow] = rb.x; Bs[nb][lk4 + 1][lrow] = rb.y;
            Bs[nb][lk4 + 2][lrow] = rb.z; Bs[nb][lk4 + 3][lrow] = rb.w;
            __syncthreads();
            buf = nb;
        }
    }

    const int n0 = bn + tx * 8;
    #pragma unroll
    for (int i = 0; i < 8; i++) {
        int m = bm + ty * 8 + i;
        float v[8];
        #pragma unroll
        for (int j = 0; j < 4; j++) {
            unsigned lo, hi;
            asm("mov.b64 {%0, %1}, %2;" : "=r"(lo), "=r"(hi) : "l"(acc[i][j]));
            v[2 * j]     = __uint_as_float(lo);
            v[2 * j + 1] = __uint_as_float(hi);
        }
        long base = (long)m * NTOKEN + n0;
        if (n0 + 8 <= NTOKEN) {
            #pragma unroll
            for (int j = 0; j < 8; j++) v[j] += bias[n0 + j];
            *(float4*)(C + base)     = make_float4(v[0], v[1], v[2], v[3]);
            *(float4*)(C + base + 4) = make_float4(v[4], v[5], v[6], v[7]);
        } else {
            for (int j = 0; j < 8; j++)
                if (n0 + j < NTOKEN) C[base + j] = v[j] + bias[n0 + j];
        }
    }
}

// -------------------- tail: hx_final + scalar loss, if d_out carries them --------------------
__global__ void tail_kernel(float* __restrict__ out, int out_size) {
    int i = blockIdx.x * blockDim.x + threadIdx.x;
    if (i < HX_ELEMS && (long)out_size >= DEC_ELEMS + HX_ELEMS)
        out[DEC_ELEMS + i] = g_outputs[(long)(T_STEPS - 1) * HX_ELEMS + i];
    if (i == 0 && (long)out_size >= DEC_ELEMS + HX_ELEMS + 1)
        out[DEC_ELEMS + HX_ELEMS] = 0.0f;
}

extern "C" void kernel_launch(void* const* d_in, const int* in_sizes, int n_in,
                              void* d_out, int out_size) {
    const int*   input      = (const int*)  d_in[0];
    const float* hidden     = (const float*)d_in[1];
    const float* encoder_w  = (const float*)d_in[2];
    const float* inp_wq     = (const float*)d_in[3];
    const float* inp_wk     = (const float*)d_in[4];
    const float* inp_wv     = (const float*)d_in[5];
    const float* inp_fc_w   = (const float*)d_in[6];
    const float* inp_fc_b   = (const float*)d_in[7];
    const float* mha_wq     = (const float*)d_in[8];
    const float* mha_wk     = (const float*)d_in[9];
    const float* mha_wv     = (const float*)d_in[10];
    const float* mha_fc_w   = (const float*)d_in[11];
    const float* mha_fc_b   = (const float*)d_in[12];
    const float* mha_gate_w = (const float*)d_in[13];
    const float* mha_gate_b = (const float*)d_in[14];
    const float* gru_w_ih   = (const float*)d_in[15];
    const float* gru_w_hh   = (const float*)d_in[16];
    const float* gru_b_ih   = (const float*)d_in[17];
    const float* gru_b_hh   = (const float*)d_in[18];
    const float* dec_w      = (const float*)d_in[19];
    const float* dec_b      = (const float*)d_in[20];
    float* out = (float*)d_out;

    cudaFuncSetAttribute(rnn_kernel, cudaFuncAttributeMaxDynamicSharedMemorySize, SMEM_BYTES);

    prep_kernel<<<704, 256>>>(gru_w_ih, gru_w_hh, mha_fc_w, mha_gate_w);

    rnn_kernel<<<BATCH / 2, 1024, SMEM_BYTES>>>(input, hidden, encoder_w,
                                inp_wq, inp_wk, inp_wv, inp_fc_w, inp_fc_b,
                                mha_wq, mha_wk, mha_wv, mha_fc_b, mha_gate_b,
                                gru_b_ih, gru_b_hh);

    dim3 dgrid((NTOKEN + 127) / 128, (T_STEPS * BATCH) / 128);
    dec_kernel<<<dgrid, 256>>>(dec_w, dec_b, out);

    tail_kernel<<<(HX_ELEMS + 255) / 256, 256>>>(out, out_size);
}

// round 13
// speedup vs baseline: 1.8775x; 1.4282x over previous
#include <cuda_runtime.h>
#include <cuda_bf16.h>
#include <math.h>

// Problem constants
#define T_STEPS 128
#define BATCH   64
#define NTOKEN  10000
#define NB      6
#define BS      100
#define NHID    600          // NB*BS
#define EMHA    64           // NH_MHA*DK_MHA
#define DEC_ELEMS 81920000L  // T*B*NTOKEN
#define HX_ELEMS  38400      // B*NHID

#define N_RNN_CTAS 32
#define N_NTILES   79        // ceil(10000/128)
#define N_MTILES   64        // 8192/128

// -------------------- device scratch (no allocations allowed) --------------------
__device__ float g_outputs[T_STEPS * BATCH * NHID];   // hx per step, row = t*64+b
__device__ float g_gruT_ih[NB * BS * 3 * BS];         // [k][d][g]  (6,100,300)
__device__ float g_gruT_hh[NB * BS * 3 * BS];
__device__ float g_mhafcT[EMHA * BS];                 // [e][i]  (64,100)
__device__ float g_gateT[EMHA * BS];
__device__ int   g_flag[T_STEPS];                     // per-step completion count (0..32)

// -------------------- one-time weight transposes + flag reset --------------------
__global__ void prep_kernel(const float* __restrict__ w_ih, const float* __restrict__ w_hh,
                            const float* __restrict__ mfc, const float* __restrict__ mgate) {
    int i = blockIdx.x * blockDim.x + threadIdx.x;
    if (i < T_STEPS) g_flag[i] = 0;
    if (i < NB * 3 * BS * BS) {               // 180000: (6,300,100) -> (6,100,300)
        int k = i / (3 * BS * BS);
        int r = i % (3 * BS * BS);
        int g = r / BS;
        int d = r % BS;
        int dst = k * (BS * 3 * BS) + d * (3 * BS) + g;
        g_gruT_ih[dst] = w_ih[i];
        g_gruT_hh[dst] = w_hh[i];
    }
    if (i < BS * EMHA) {                      // 6400: (100,64) -> (64,100)
        int r = i / EMHA;
        int e = i % EMHA;
        g_mhafcT[e * BS + r] = mfc[i];
        g_gateT[e * BS + r]  = mgate[i];
    }
}

// -------------------- helpers --------------------
__device__ __forceinline__ float sigmoidf_(float x) { return 1.f / (1.f + expf(-x)); }
__device__ __forceinline__ void ffma2(unsigned long long& a, unsigned long long x, unsigned long long y) {
    asm("fma.rn.f32x2 %0, %1, %2, %0;" : "+l"(a) : "l"(x), "l"(y));
}
__device__ __forceinline__ unsigned long long bc2(float x) {
    unsigned long long r;
    asm("mov.b64 %0, {%1, %1};" : "=l"(r) : "r"(__float_as_uint(x)));
    return r;
}
__device__ __forceinline__ float2 up2(unsigned long long a) {
    unsigned lo, hi;
    asm("mov.b64 {%0, %1}, %2;" : "=r"(lo), "=r"(hi) : "l"(a));
    return make_float2(__uint_as_float(lo), __uint_as_float(hi));
}

// -------------------- smem layout (floats) for the rnn path --------------------
#define OFF_HX    0        // [2][600]
#define OFF_X     1200     // [2][600]
#define OFF_IU    2400     // [2][600]
#define OFF_HN    3600     // [2][600]
#define OFF_GX    4800     // [2][1800]
#define OFF_GH    8400     // [2][1800]
#define OFF_RED   12000    // 8192
#define OFF_QKVP  20192    // [2part][2b][1152]
#define OFF_QKV   24800    // [2][1152]
#define OFF_K0    27104    // [2][128]
#define OFF_V0    27360    // [2][128]
#define OFF_QP    27616    // [2][768]
#define OFF_P     29152    // [2][104]
#define OFF_A0    29360    // [2][8]
#define OFF_MASK  29376    // [2][8]
#define OFF_AW    29392    // [2][144]
#define OFF_AO    29680    // [2][384]
#define OFF_FCT   30448    // 6400
#define OFF_GT    36848    // 6400
#define OFF_TOK   43248    // 256 ints
#define SMEM_FLOATS 43504
#define SMEM_BYTES  (SMEM_FLOATS * 4)

// ============================================================================
// Fused kernel: blocks [0,32) run the recurrence (2 batches each);
// blocks [32, 32+64*79) run decoder tiles gated by per-step flags.
// Every CTA requests the full 174KB dynamic smem => 1 CTA/SM, so the 32 rnn
// CTAs are guaranteed resident in wave 1 and can never be starved by spinning
// decoder CTAs (deadlock-free by construction).
// ============================================================================
__global__ __launch_bounds__(1024, 1)
void fused_kernel(const int* __restrict__ input, const float* __restrict__ hidden,
                  const float* __restrict__ enc,
                  const float* __restrict__ wq,     // (6,100,128)
                  const float* __restrict__ wk,     // (2,600,128) slab 0 used
                  const float* __restrict__ wv,     // (2,600,128) slab 0 used
                  const float* __restrict__ fc_w,   // (100,128)
                  const float* __restrict__ fc_b,   // (100,)
                  const float* __restrict__ mwq,    // (6,100,64)
                  const float* __restrict__ mwk,
                  const float* __restrict__ mwv,
                  const float* __restrict__ mfc_b,  // (100,)
                  const float* __restrict__ mg_b,   // (100,)
                  const float* __restrict__ b_ih,   // (6,300)
                  const float* __restrict__ b_hh,   // (6,300)
                  const float* __restrict__ Bw,     // dec_w (10000,600)
                  const float* __restrict__ bias,   // dec_b (10000,)
                  float* __restrict__ C)            // out (8192,10000)
{
    extern __shared__ float smem[];
    const int tid = threadIdx.x;

    if (blockIdx.x >= N_RNN_CTAS) {
        // ================= decoder path =================
        const int d  = blockIdx.x - N_RNN_CTAS;
        const int mt = d / N_NTILES, nt = d % N_NTILES;
        const int bm = mt * 128, bn = nt * 128;

        if (tid >= 512) return;   // 512 active threads per dec tile

        if (tid == 0) {
            while (atomicAdd(&g_flag[2 * mt], 0)     < N_RNN_CTAS) __nanosleep(256);
            while (atomicAdd(&g_flag[2 * mt + 1], 0) < N_RNN_CTAS) __nanosleep(256);
            __threadfence();
        }
        asm volatile("bar.sync 1, 512;" ::: "memory");

        float* As = smem;          // [2][8][128]
        float* Bs = smem + 2048;   // [2][8][128]

        const int arow = tid >> 2;          // 0..127
        const int kp   = (tid & 3) * 2;     // 0,2,4,6
        const float* Ap = g_outputs + (long)(bm + arow) * NHID + kp;
        int brow = bn + arow; if (brow > NTOKEN - 1) brow = NTOKEN - 1;
        const float* Bp = Bw + (long)brow * NHID + kp;

        const int tx = tid & 15, ty = tid >> 4;   // 16 x 32

        unsigned long long acc[4][4];
        #pragma unroll
        for (int i = 0; i < 4; i++)
            #pragma unroll
            for (int j = 0; j < 4; j++) acc[i][j] = 0ull;

        float2 ra = *(const float2*)Ap;
        float2 rb = *(const float2*)Bp;
        int buf = 0;
        As[(0 * 8 + kp) * 128 + arow]     = ra.x;
        As[(0 * 8 + kp + 1) * 128 + arow] = ra.y;
        Bs[(0 * 8 + kp) * 128 + arow]     = rb.x;
        Bs[(0 * 8 + kp + 1) * 128 + arow] = rb.y;
        asm volatile("bar.sync 1, 512;" ::: "memory");

        const int NKT = NHID / 8;   // 75
        for (int kt = 0; kt < NKT; kt++) {
            if (kt < NKT - 1) {
                ra = *(const float2*)(Ap + (kt + 1) * 8);
                rb = *(const float2*)(Bp + (kt + 1) * 8);
            }
            #pragma unroll
            for (int kk = 0; kk < 8; kk++) {
                float4 a = *(const float4*)(As + (buf * 8 + kk) * 128 + ty * 4);
                ulonglong2 b0 = *(const ulonglong2*)(Bs + (buf * 8 + kk) * 128 + tx * 8);
                ulonglong2 b1 = *(const ulonglong2*)(Bs + (buf * 8 + kk) * 128 + tx * 8 + 4);
                float av[4] = {a.x, a.y, a.z, a.w};
                unsigned long long bbv[4] = {b0.x, b0.y, b1.x, b1.y};
                #pragma unroll
                for (int i = 0; i < 4; i++) {
                    unsigned long long aa = bc2(av[i]);
                    #pragma unroll
                    for (int j = 0; j < 4; j++) ffma2(acc[i][j], aa, bbv[j]);
                }
            }
            if (kt < NKT - 1) {
                int nb = buf ^ 1;
                As[(nb * 8 + kp) * 128 + arow]     = ra.x;
                As[(nb * 8 + kp + 1) * 128 + arow] = ra.y;
                Bs[(nb * 8 + kp) * 128 + arow]     = rb.x;
                Bs[(nb * 8 + kp + 1) * 128 + arow] = rb.y;
                asm volatile("bar.sync 1, 512;" ::: "memory");
                buf = nb;
            }
        }

        const int n0 = bn + tx * 8;
        #pragma unroll
        for (int i = 0; i < 4; i++) {
            int m = bm + ty * 4 + i;
            float v[8];
            #pragma unroll
            for (int j = 0; j < 4; j++) {
                float2 p = up2(acc[i][j]);
                v[2 * j] = p.x; v[2 * j + 1] = p.y;
            }
            long base = (long)m * NTOKEN + n0;
            if (n0 + 8 <= NTOKEN) {
                #pragma unroll
                for (int j = 0; j < 8; j++) v[j] += bias[n0 + j];
                *(float4*)(C + base)     = make_float4(v[0], v[1], v[2], v[3]);
                *(float4*)(C + base + 4) = make_float4(v[4], v[5], v[6], v[7]);
            } else {
                for (int j = 0; j < 8; j++)
                    if (n0 + j < NTOKEN) C[base + j] = v[j] + bias[n0 + j];
            }
        }
        return;
    }

    // ================= rnn path =================
    const int b0 = blockIdx.x * 2;

    float* s_hx   = smem + OFF_HX;
    float* s_x    = smem + OFF_X;
    float* s_iu   = smem + OFF_IU;
    float* s_hn   = smem + OFF_HN;
    float* s_gx   = smem + OFF_GX;
    float* s_gh   = smem + OFF_GH;
    float* s_red  = smem + OFF_RED;
    float* s_qkvp = smem + OFF_QKVP;
    float* s_qkv  = smem + OFF_QKV;
    float* s_k0   = smem + OFF_K0;
    float* s_v0   = smem + OFF_V0;
    float* s_qp   = smem + OFF_QP;
    float* s_p    = smem + OFF_P;
    float* s_a0   = smem + OFF_A0;
    float* s_mask = smem + OFF_MASK;
    float* s_aw   = smem + OFF_AW;
    float* s_ao   = smem + OFF_AO;
    float* s_fcT  = smem + OFF_FCT;
    float* s_gT   = smem + OFF_GT;
    int*   s_tok  = (int*)(smem + OFF_TOK);

    // preload: hx, cached fc/gate transposes, all tokens
    for (int j = tid; j < 1200; j += 1024)
        s_hx[j] = hidden[(long)(b0 + j / 600) * NHID + (j % 600)];
    for (int j = tid; j < 6400; j += 1024) {
        s_fcT[j] = g_mhafcT[j];
        s_gT[j]  = g_gateT[j];
    }
    if (tid < 256) {
        int t = tid >> 1, bb = tid & 1;
        s_tok[tid] = input[t * BATCH + b0 + bb];
    }
    __syncthreads();

    const int w    = tid >> 5;
    const int lane = tid & 31;
    const int l4   = lane * 4;

    for (int t = 0; t < T_STEPS; t++) {
        // ---- P0: embedding load (float4) ----
        if (tid < 300) {
            int bb = tid / 150, j = tid % 150;
            long tok = s_tok[t * 2 + bb];
            *(float4*)(s_x + bb * 600 + j * 4) = *(const float4*)(enc + tok * NHID + j * 4);
        }
        __syncthreads();

        // ---- Phase A: k0/v0 partials (warps 0-19) + q_proj partials (warps 20-31) ----
        if (w < 20) {
            int kv = w / 10, ws = w % 10;
            const float* W = kv ? wv : wk;   // slab 0
            unsigned long long a00 = 0, a01 = 0, a10 = 0, a11 = 0;
            for (int d = ws; d < 600; d += 10) {
                ulonglong2 wt = *(const ulonglong2*)(W + d * 128 + l4);
                unsigned long long x0 = bc2(s_x[d]);
                unsigned long long x1 = bc2(s_x[600 + d]);
                ffma2(a00, x0, wt.x); ffma2(a01, x0, wt.y);
                ffma2(a10, x1, wt.x); ffma2(a11, x1, wt.y);
            }
            float2 p0 = up2(a00), p1 = up2(a01);
            *(float4*)(s_red + ((kv * 10 + ws) * 2 + 0) * 128 + l4) = make_float4(p0.x, p0.y, p1.x, p1.y);
            p0 = up2(a10); p1 = up2(a11);
            *(float4*)(s_red + ((kv * 10 + ws) * 2 + 1) * 128 + l4) = make_float4(p0.x, p0.y, p1.x, p1.y);
        } else {
            int u = w - 20, n = u >> 1, dp = u & 1;
            const float* W  = wq + (n * 100 + dp * 50) * 128;
            const float* h0 = s_hx + n * 100 + dp * 50;
            unsigned long long a00 = 0, a01 = 0, a10 = 0, a11 = 0;
            #pragma unroll 2
            for (int d = 0; d < 50; d++) {
                ulonglong2 wt = *(const ulonglong2*)(W + d * 128 + l4);
                unsigned long long x0 = bc2(h0[d]);
                unsigned long long x1 = bc2(h0[600 + d]);
                ffma2(a00, x0, wt.x); ffma2(a01, x0, wt.y);
                ffma2(a10, x1, wt.x); ffma2(a11, x1, wt.y);
            }
            float2 p0 = up2(a00), p1 = up2(a01);
            *(float4*)(s_red + 5120 + ((n * 2 + dp) * 2 + 0) * 128 + l4) = make_float4(p0.x, p0.y, p1.x, p1.y);
            p0 = up2(a10); p1 = up2(a11);
            *(float4*)(s_red + 5120 + ((n * 2 + dp) * 2 + 1) * 128 + l4) = make_float4(p0.x, p0.y, p1.x, p1.y);
        }
        __syncthreads();

        // ---- Reduce: k0/v0 (sum 10) and qp (sum 2) ----
        for (int j = tid; j < 2048; j += 1024) {
            if (j < 512) {
                int kv = j >> 8, bb = (j >> 7) & 1, e = j & 127;
                float s = 0.f;
                #pragma unroll
                for (int ws = 0; ws < 10; ws++) s += s_red[((kv * 10 + ws) * 2 + bb) * 128 + e];
                (kv ? s_v0 : s_k0)[bb * 128 + e] = s;
            } else {
                int q = j - 512;
                int n = q >> 8, bb = (q >> 7) & 1, e = q & 127;
                s_qp[bb * 768 + n * 128 + e] =
                    s_red[5120 + ((n * 2 + 0) * 2 + bb) * 128 + e] +
                    s_red[5120 + ((n * 2 + 1) * 2 + bb) * 128 + e];
            }
        }
        __syncthreads();

        // ---- P2: scores (warps 0-11) + p = v0 @ fc^T (warps 12-31) ----
        if (w < 12) {
            int bb = w / 6, n = w % 6;
            const float* qv = s_qp + bb * 768 + n * 128;
            const float* k0 = s_k0 + bb * 128;
            float acc = qv[lane] * k0[lane] + qv[lane + 32] * k0[lane + 32]
                      + qv[lane + 64] * k0[lane + 64] + qv[lane + 96] * k0[lane + 96];
            #pragma unroll
            for (int o = 16; o > 0; o >>= 1) acc += __shfl_xor_sync(0xffffffffu, acc, o);
            if (lane == 0) s_a0[bb * 8 + n] = sigmoidf_(acc * 0.08838834764831845f);
        } else {
            int base = (w - 12) * 10;
            #pragma unroll 2
            for (int r = 0; r < 10; r++) {
                int pair = base + r;
                int bb = pair / 100, i = pair % 100;
                float4 f = *(const float4*)(fc_w + i * 128 + l4);
                const float* vv = s_v0 + bb * 128 + l4;
                float acc = f.x * vv[0] + f.y * vv[1] + f.z * vv[2] + f.w * vv[3];
                #pragma unroll
                for (int o = 16; o > 0; o >>= 1) acc += __shfl_xor_sync(0xffffffffu, acc, o);
                if (lane == 0) s_p[bb * 104 + i] = acc;
            }
        }
        __syncthreads();

        // ---- P2b: top-k mask + inp_use ----
        if (tid < 2) {
            int bb = tid;
            float v[6];
            #pragma unroll
            for (int n = 0; n < 6; n++) v[n] = s_a0[bb * 8 + n];
            #pragma unroll
            for (int a = 0; a < 6; a++)
                #pragma unroll
                for (int c = a + 1; c < 6; c++)
                    if (v[c] > v[a]) { float tmp = v[a]; v[a] = v[c]; v[c] = tmp; }
            float thr = v[3] - 0.01f;
            #pragma unroll
            for (int n = 0; n < 6; n++) s_mask[bb * 8 + n] = (s_a0[bb * 8 + n] > thr) ? 1.f : 0.f;
        }
        for (int j = tid; j < 1200; j += 1024) {
            int bb = j / 600, i = j % 600, n = i / 100, ii = i % 100;
            s_iu[bb * 600 + i] = s_a0[bb * 8 + n] * s_p[bb * 104 + ii] + fc_b[ii];
        }
        __syncthreads();

        // ---- P4: GRU gate matvecs (900 tasks, 4 outputs x 2 batches each) ----
        if (tid < 900) {
            int h = tid / 450, r = tid % 450, k = r / 75, g = (r % 75) * 4;
            const float* WT = (h ? g_gruT_hh : g_gruT_ih) + k * 30000 + g;
            const float* s0 = (h ? s_hx : s_iu) + k * 100;
            const float* bias2 = (h ? b_hh : b_ih) + k * 300 + g;
            unsigned long long a00 = 0, a01 = 0, a10 = 0, a11 = 0;
            #pragma unroll 4
            for (int d = 0; d < 100; d++) {
                ulonglong2 wt = *(const ulonglong2*)(WT + d * 300);
                unsigned long long x0 = bc2(s0[d]);
                unsigned long long x1 = bc2(s0[600 + d]);
                ffma2(a00, x0, wt.x); ffma2(a01, x0, wt.y);
                ffma2(a10, x1, wt.x); ffma2(a11, x1, wt.y);
            }
            float4 bi = *(const float4*)bias2;
            float* dst = h ? s_gh : s_gx;
            float2 p0 = up2(a00), p1 = up2(a01);
            *(float4*)(dst + k * 300 + g) =
                make_float4(p0.x + bi.x, p0.y + bi.y, p1.x + bi.z, p1.y + bi.w);
            p0 = up2(a10); p1 = up2(a11);
            *(float4*)(dst + 1800 + k * 300 + g) =
                make_float4(p0.x + bi.x, p0.y + bi.y, p1.x + bi.z, p1.y + bi.w);
        }
        __syncthreads();

        // ---- P5: GRU elementwise ----
        for (int j = tid; j < 1200; j += 1024) {
            int bb = j / 600, i = j % 600, k = i / 100, jj = i % 100;
            int base = bb * 1800 + k * 300 + jj;
            float r  = sigmoidf_(s_gx[base]       + s_gh[base]);
            float z  = sigmoidf_(s_gx[base + 100] + s_gh[base + 100]);
            float nn = tanhf(s_gx[base + 200] + r * s_gh[base + 200]);
            s_hn[bb * 600 + i] = (1.f - z) * nn + z * s_hx[bb * 600 + i];
        }
        __syncthreads();

        // ---- P6: MHA q/k/v projections (576 tasks, d split 2) ----
        if (tid < 576) {
            int part = tid / 288, r = tid % 288;
            int which = r / 96, n = (r % 96) / 16, e4 = (r % 16) * 4;
            const float* W = (which == 0 ? mwq : (which == 1 ? mwk : mwv))
                             + (n * 100 + part * 50) * 64 + e4;
            const float* h0 = s_hn + n * 100 + part * 50;
            unsigned long long a00 = 0, a01 = 0, a10 = 0, a11 = 0;
            #pragma unroll 2
            for (int d = 0; d < 50; d++) {
                ulonglong2 wt = *(const ulonglong2*)(W + d * 64);
                unsigned long long x0 = bc2(h0[d]);
                unsigned long long x1 = bc2(h0[600 + d]);
                ffma2(a00, x0, wt.x); ffma2(a01, x0, wt.y);
                ffma2(a10, x1, wt.x); ffma2(a11, x1, wt.y);
            }
            int o = which * 384 + n * 64 + e4;
            float2 p0 = up2(a00), p1 = up2(a01);
            *(float4*)(s_qkvp + (part * 2 + 0) * 1152 + o) = make_float4(p0.x, p0.y, p1.x, p1.y);
            p0 = up2(a10); p1 = up2(a11);
            *(float4*)(s_qkvp + (part * 2 + 1) * 1152 + o) = make_float4(p0.x, p0.y, p1.x, p1.y);
        }
        __syncthreads();
        for (int j = tid; j < 2304; j += 1024) {
            int bb = j / 1152, o = j % 1152;
            s_qkv[bb * 1152 + o] = s_qkvp[(0 * 2 + bb) * 1152 + o] + s_qkvp[(1 * 2 + bb) * 1152 + o];
        }
        __syncthreads();

        // ---- P7: attention scores + softmax ----
        if (tid < 288) {
            int bb = tid / 144, r = tid % 144, h = r / 36, i = (r % 36) / 6, j = r % 6;
            const float* qv = s_qkv + bb * 1152 + i * 64 + h * 16;
            const float* kk = s_qkv + bb * 1152 + 384 + j * 64 + h * 16;
            float acc = 0.f;
            #pragma unroll
            for (int d2 = 0; d2 < 16; d2++) acc += qv[d2] * kk[d2];
            s_aw[bb * 144 + h * 36 + i * 6 + j] = acc * 0.25f;
        }
        __syncthreads();
        if (tid < 48) {
            int bb = tid / 24, h = (tid % 24) / 6, i = tid % 6;
            float* row = s_aw + bb * 144 + h * 36 + i * 6;
            float m = row[0];
            #pragma unroll
            for (int j = 1; j < 6; j++) m = fmaxf(m, row[j]);
            float ex[6]; float ssum = 0.f;
            #pragma unroll
            for (int j = 0; j < 6; j++) { ex[j] = expf(row[j] - m); ssum += ex[j]; }
            float inv = 1.f / ssum;
            #pragma unroll
            for (int j = 0; j < 6; j++) row[j] = ex[j] * inv;
        }
        __syncthreads();

        // ---- P8: attn @ V ----
        if (tid < 768) {
            int bb = tid / 384, r = tid % 384, n = r / 64, e = r % 64, h = e / 16;
            const float* aw = s_aw + bb * 144 + h * 36 + n * 6;
            const float* vm = s_qkv + bb * 1152 + 768 + e;
            float acc = 0.f;
            #pragma unroll
            for (int j = 0; j < 6; j++) acc += aw[j] * vm[j * 64];
            s_ao[bb * 384 + r] = acc;
        }
        __syncthreads();

        // ---- P9: fc proj + gate + masked blend, write output ----
        if (tid < 300) {
            int bb = tid / 150, r = tid % 150, n = r / 25, i4 = (r % 25) * 4;
            const float* ao = s_ao + bb * 384 + n * 64;
            unsigned long long pr0 = 0, pr1 = 0, gt0 = 0, gt1 = 0;
            #pragma unroll 4
            for (int e = 0; e < 64; e++) {
                ulonglong2 f = *(const ulonglong2*)(s_fcT + e * 100 + i4);
                ulonglong2 g = *(const ulonglong2*)(s_gT + e * 100 + i4);
                unsigned long long a2 = bc2(ao[e]);
                ffma2(pr0, a2, f.x); ffma2(pr1, a2, f.y);
                ffma2(gt0, a2, g.x); ffma2(gt1, a2, g.y);
            }
            float2 pa = up2(pr0), pb = up2(pr1), ga = up2(gt0), gb = up2(gt1);
            float prv[4] = {pa.x, pa.y, pb.x, pb.y};
            float gtv[4] = {ga.x, ga.y, gb.x, gb.y};
            float m = s_mask[bb * 8 + n];
            float4 o4;
            float* ov = (float*)&o4;
            #pragma unroll
            for (int c = 0; c < 4; c++) {
                int i = i4 + c;
                float pr = prv[c] + mfc_b[i];
                float gt = gtv[c] + mg_b[i];
                float hatt = sigmoidf_(gt) * tanhf(pr);
                int hidx = bb * 600 + n * 100 + i;
                float nh = m * hatt + (1.f - m) * s_hx[hidx];
                s_hx[hidx] = nh;
                ov[c] = nh;
            }
            *(float4*)(g_outputs + ((long)t * BATCH + b0 + bb) * NHID + n * 100 + i4) = o4;
        }
        // release step t to decoder CTAs: fence all stores, sync, one atomic
        __threadfence();
        __syncthreads();
        if (tid == 0) atomicAdd(&g_flag[t], 1);
    }
}

// -------------------- tail: hx_final + scalar loss, if d_out carries them --------------------
__global__ void tail_kernel(float* __restrict__ out, int out_size) {
    int i = blockIdx.x * blockDim.x + threadIdx.x;
    if (i < HX_ELEMS && (long)out_size >= DEC_ELEMS + HX_ELEMS)
        out[DEC_ELEMS + i] = g_outputs[(long)(T_STEPS - 1) * HX_ELEMS + i];
    if (i == 0 && (long)out_size >= DEC_ELEMS + HX_ELEMS + 1)
        out[DEC_ELEMS + HX_ELEMS] = 0.0f;
}

extern "C" void kernel_launch(void* const* d_in, const int* in_sizes, int n_in,
                              void* d_out, int out_size) {
    const int*   input      = (const int*)  d_in[0];
    const float* hidden     = (const float*)d_in[1];
    const float* encoder_w  = (const float*)d_in[2];
    const float* inp_wq     = (const float*)d_in[3];
    const float* inp_wk     = (const float*)d_in[4];
    const float* inp_wv     = (const float*)d_in[5];
    const float* inp_fc_w   = (const float*)d_in[6];
    const float* inp_fc_b   = (const float*)d_in[7];
    const float* mha_wq     = (const float*)d_in[8];
    const float* mha_wk     = (const float*)d_in[9];
    const float* mha_wv     = (const float*)d_in[10];
    const float* mha_fc_w   = (const float*)d_in[11];
    const float* mha_fc_b   = (const float*)d_in[12];
    const float* mha_gate_w = (const float*)d_in[13];
    const float* mha_gate_b = (const float*)d_in[14];
    const float* gru_w_ih   = (const float*)d_in[15];
    const float* gru_w_hh   = (const float*)d_in[16];
    const float* gru_b_ih   = (const float*)d_in[17];
    const float* gru_b_hh   = (const float*)d_in[18];
    const float* dec_w      = (const float*)d_in[19];
    const float* dec_b      = (const float*)d_in[20];
    float* out = (float*)d_out;

    cudaFuncSetAttribute(fused_kernel, cudaFuncAttributeMaxDynamicSharedMemorySize, SMEM_BYTES);

    prep_kernel<<<704, 256>>>(gru_w_ih, gru_w_hh, mha_fc_w, mha_gate_w);

    const int grid = N_RNN_CTAS + N_MTILES * N_NTILES;   // 32 + 5056
    fused_kernel<<<grid, 1024, SMEM_BYTES>>>(input, hidden, encoder_w,
                                inp_wq, inp_wk, inp_wv, inp_fc_w, inp_fc_b,
                                mha_wq, mha_wk, mha_wv, mha_fc_b, mha_gate_b,
                                gru_b_ih, gru_b_hh,
                                dec_w, dec_b, out);

    tail_kernel<<<(HX_ELEMS + 255) / 256, 256>>>(out, out_size);
}